// round 11
// baseline (speedup 1.0000x reference)
#include <cuda_runtime.h>
#include <cstdint>

// Problem constants
#define B_ 2
#define T_ 2048
#define E_ 1024
#define H_ 16
#define D_ 64
#define BT_ (B_ * T_)

// Scratch (allocation-free: __device__ globals). All tf32-valued fp32 bits.
__device__ float g_q[(size_t)B_ * H_ * T_ * D_];
__device__ float g_k[(size_t)B_ * H_ * T_ * D_];
__device__ float g_v[(size_t)B_ * H_ * T_ * D_];
__device__ float g_att[(size_t)BT_ * E_];
__device__ float g_xr[(size_t)BT_ * E_];
__device__ float g_wqkvr[(size_t)3 * E_ * E_];
__device__ float g_wprojr[(size_t)E_ * E_];

// ---------------------------------------------------------------------------
__device__ __forceinline__ uint32_t smem_u32(const void* p) {
    uint32_t a;
    asm("{ .reg .u64 t; cvta.to.shared.u64 t, %1; cvt.u32.u64 %0, t; }" : "=r"(a) : "l"(p));
    return a;
}
__device__ __forceinline__ uint32_t tf32u(float x) {
    uint32_t r;
    asm("cvt.rna.tf32.f32 %0, %1;" : "=r"(r) : "f"(x));
    return r;
}
__device__ __forceinline__ float ex2(float x) {
    float r;
    asm("ex2.approx.f32 %0, %1;" : "=f"(r) : "f"(x));
    return r;
}
__device__ __forceinline__ void mma_tf32(float* c, const uint32_t* a, const uint32_t* b) {
    asm volatile(
        "mma.sync.aligned.m16n8k8.row.col.f32.tf32.tf32.f32 "
        "{%0,%1,%2,%3}, {%4,%5,%6,%7}, {%8,%9}, {%0,%1,%2,%3};"
        : "+f"(c[0]), "+f"(c[1]), "+f"(c[2]), "+f"(c[3])
        : "r"(a[0]), "r"(a[1]), "r"(a[2]), "r"(a[3]), "r"(b[0]), "r"(b[1]));
}
__device__ __forceinline__ void ldmx4(uint32_t* r, uint32_t a) {
    asm volatile("ldmatrix.sync.aligned.m8n8.x4.shared.b16 {%0,%1,%2,%3}, [%4];"
                 : "=r"(r[0]), "=r"(r[1]), "=r"(r[2]), "=r"(r[3]) : "r"(a));
}
__device__ __forceinline__ void cpa16(uint32_t s, const void* g) {
    asm volatile("cp.async.cg.shared.global [%0], [%1], 16;" :: "r"(s), "l"(g) : "memory");
}
#define CP_COMMIT() asm volatile("cp.async.commit_group;" ::: "memory")
#define CP_WAIT(n) asm volatile("cp.async.wait_group %0;" :: "n"(n) : "memory")

// ---------------------------------------------------------------------------
// Prep: one kernel rounds x, w_qkv, w_proj to tf32 (RNA). f4 segments:
// x: [0, 1048576), wqkv: [1048576, 1835008), wproj: [1835008, 2097152)
// ---------------------------------------------------------------------------
__global__ void __launch_bounds__(256) round_all(const float* __restrict__ x,
                                                 const float* __restrict__ wq,
                                                 const float* __restrict__ wp) {
    const size_t f4 = (size_t)blockIdx.x * 256 + threadIdx.x;
    const float* src;
    float* dst;
    size_t off;
    if (f4 < 1048576) { src = x; dst = g_xr; off = f4; }
    else if (f4 < 1835008) { src = wq; dst = g_wqkvr; off = f4 - 1048576; }
    else { src = wp; dst = g_wprojr; off = f4 - 1835008; }
    const size_t i = off * 4;
    float4 v = *(const float4*)(src + i);
    *(uint4*)(dst + i) = make_uint4(tf32u(v.x), tf32u(v.y), tf32u(v.z), tf32u(v.w));
}

// ---------------------------------------------------------------------------
// TF32 mma.sync GEMM. BMt x 128 CTA tile, THREADS = BMt (BMt/64 x 2 warps,
// warp tile 64x64). BK=32, 2-stage cp.async, ldmatrix fragments.
// C[m,n] = sum_k A[m,k] * Bm[n,k]; A,B pre-rounded tf32 bits.
// MODE 0: scatter rounded into g_q/g_k/g_v. MODE 1: fp32 store to C.
// ---------------------------------------------------------------------------
#define BK 32
#define LDPG 36                       // u32 row stride (144B), conflict-free

template <int MODE, int Ntot, int Ktot, int BMt>
__global__ void __launch_bounds__(BMt) mma_gemm(const float* __restrict__ A,
                                                const float* __restrict__ Bm,
                                                float* __restrict__ C) {
    constexpr int THREADS = BMt;
    constexpr int NWM = BMt / 64;
    constexpr int STG_A = BMt * LDPG;     // u32
    constexpr int STG_B = 128 * LDPG;     // u32
    constexpr int STAGE = STG_A + STG_B;  // u32

    extern __shared__ uint32_t sm[];
    const uint32_t sb = smem_u32(sm);

    const int tid = threadIdx.x;
    const int lane = tid & 31;
    const int wid = tid >> 5;
    const int gid = lane >> 2;
    const int tig = lane & 3;
    const int wm = (wid % NWM) * 64;
    const int wn = (wid / NWM) * 64;
    const int m0 = blockIdx.y * BMt;
    const int n0 = blockIdx.x * 128;

    // Fragment base byte-offsets within a stage (ldmatrix lane mapping)
    const uint32_t aoff = ((wm + (lane & 15)) * LDPG + ((lane & 16) >> 2)) * 4;
    const uint32_t boff = ((wn + ((lane & 16) >> 1) + (lane & 7)) * LDPG + ((lane & 8) >> 1)) * 4;

    float acc[4][8][4];
#pragma unroll
    for (int i = 0; i < 4; i++)
#pragma unroll
        for (int j = 0; j < 8; j++)
#pragma unroll
            for (int v = 0; v < 4; v++) acc[i][j][v] = 0.0f;

#define ISSUE(g)                                                                       \
    do {                                                                               \
        const int _k0 = (g) * BK;                                                      \
        const uint32_t _sa = sb + ((g) & 1) * (STAGE * 4);                             \
        const uint32_t _sb2 = _sa + STG_A * 4;                                         \
        _Pragma("unroll")                                                              \
        for (int _i = 0; _i < 8; _i++) {                                               \
            const int _id = tid + _i * THREADS;                                        \
            const int _r = _id >> 3;                                                   \
            const int _c = (_id & 7) << 2;                                             \
            cpa16(_sa + (_r * LDPG + _c) * 4, A + (size_t)(m0 + _r) * Ktot + _k0 + _c); \
        }                                                                              \
        _Pragma("unroll")                                                              \
        for (int _i = 0; _i < 1024 / THREADS; _i++) {                                  \
            const int _id = tid + _i * THREADS;                                        \
            const int _r = _id >> 3;                                                   \
            const int _c = (_id & 7) << 2;                                             \
            cpa16(_sb2 + (_r * LDPG + _c) * 4, Bm + (size_t)(n0 + _r) * Ktot + _k0 + _c); \
        }                                                                              \
        CP_COMMIT();                                                                   \
    } while (0)

    ISSUE(0);

    const int NITER = Ktot / BK;
#pragma unroll 1
    for (int it = 0; it < NITER; ++it) {
        CP_WAIT(0);
        __syncthreads();
        if (it + 1 < NITER) ISSUE(it + 1);

        const uint32_t stg = sb + (it & 1) * (STAGE * 4);
        const uint32_t ab = stg + aoff;
        const uint32_t bbv = stg + STG_A * 4 + boff;

#pragma unroll
        for (int kc = 0; kc < 4; kc++) {
            uint32_t af[4][4], bb[4][4];
#pragma unroll
            for (int mi = 0; mi < 4; mi++)
                ldmx4(af[mi], ab + mi * (16 * LDPG * 4) + kc * 32);
#pragma unroll
            for (int p = 0; p < 4; p++)
                ldmx4(bb[p], bbv + p * (16 * LDPG * 4) + kc * 32);
#pragma unroll
            for (int mi = 0; mi < 4; mi++)
#pragma unroll
                for (int ni = 0; ni < 8; ni++)
                    mma_tf32(acc[mi][ni], af[mi], &bb[ni >> 1][(ni & 1) * 2]);
        }
    }
#undef ISSUE

    // Epilogue
#pragma unroll
    for (int mi = 0; mi < 4; mi++) {
#pragma unroll
        for (int ni = 0; ni < 8; ni++) {
            const int m = m0 + wm + mi * 16 + gid;
            const int n = n0 + wn + ni * 8 + 2 * tig;
            if (MODE == 0) {
                const int which = n >> 10;
                const int e = n & (E_ - 1);
                const int h = e >> 6;
                const int d = e & 63;
                float* base = (which == 0) ? g_q : (which == 1) ? g_k : g_v;
#pragma unroll
                for (int rr = 0; rr < 2; rr++) {
                    const int mm = m + rr * 8;
                    const int b = mm >> 11;
                    const int t = mm & (T_ - 1);
                    uint2 o = make_uint2(tf32u(acc[mi][ni][2 * rr]),
                                         tf32u(acc[mi][ni][2 * rr + 1]));
                    *(uint2*)((uint32_t*)base + (((size_t)(b * H_ + h) * T_ + t) * D_ + d)) = o;
                }
            } else {
#pragma unroll
                for (int rr = 0; rr < 2; rr++) {
                    const int mm = m + rr * 8;
                    *(float2*)(C + (size_t)mm * Ntot + n) =
                        make_float2(acc[mi][ni][2 * rr], acc[mi][ni][2 * rr + 1]);
                }
            }
        }
    }
}

#define GSMEM128 (2 * (128 * LDPG + 128 * LDPG) * 4)   // 73728
#define GSMEM64  (2 * (64 * LDPG + 128 * LDPG) * 4)    // 55296

// ---------------------------------------------------------------------------
// TF32 mma.sync causal flash attention.
// Block: 64 q-rows x 1 head, 128 threads (4 warps x 16 rows). K-tile 64.
// Double-buffered Ks/Vt; P never goes to smem (quad-shuffle transpose).
// smem: Ks[2][64][68] + Vt[2][64][68] = 69632 B.
// ---------------------------------------------------------------------------
#define ASTR 68
#define AQB 64
#define AKB 64
#define SCL2E 0.18033688011112042f   // (1/8) * log2(e)
#define ASMEM (4 * 64 * ASTR * 4)

__global__ void __launch_bounds__(128) attn_mma() {
    extern __shared__ uint32_t sm[];
    const uint32_t sb = smem_u32(sm);

    const int tid = threadIdx.x;
    const int wid = tid >> 5;
    const int lane = tid & 31;
    const int gid = lane >> 2;
    const int tig = lane & 3;

    const int bh = blockIdx.y;
    const int qb = gridDim.x - 1 - blockIdx.x;   // heavy blocks first
    const int q0 = qb * AQB;
    const int r1 = q0 + wid * 16 + gid;
    const int r2 = r1 + 8;

    // ldmatrix fragment byte-offset for K/Vt B-fragments
    const uint32_t nkoff = ((((lane & 16) >> 1) + (lane & 7)) * ASTR + ((lane & 8) >> 1)) * 4;

    const uint32_t* kbase = (const uint32_t*)(g_k + (size_t)bh * T_ * D_);
    const uint32_t* vbase = (const uint32_t*)(g_v + (size_t)bh * T_ * D_);

    // Q fragments (pre-rounded bits, held for whole block)
    uint32_t qf[8][4];
    {
        const uint32_t* q1 = (const uint32_t*)(g_q) + ((size_t)bh * T_ + r1) * D_;
        const uint32_t* q2 = (const uint32_t*)(g_q) + ((size_t)bh * T_ + r2) * D_;
#pragma unroll
        for (int kc = 0; kc < 8; kc++) {
            qf[kc][0] = q1[kc * 8 + tig];
            qf[kc][1] = q2[kc * 8 + tig];
            qf[kc][2] = q1[kc * 8 + tig + 4];
            qf[kc][3] = q2[kc * 8 + tig + 4];
        }
    }

    float o[8][4];
#pragma unroll
    for (int i = 0; i < 8; i++)
#pragma unroll
        for (int v = 0; v < 4; v++) o[i][v] = 0.0f;
    float m1 = __int_as_float(0xff800000), m2 = __int_as_float(0xff800000);
    float l1 = 0.0f, l2 = 0.0f;

#define LOADK(kt, buf)                                                                 \
    do {                                                                               \
        const int _j0 = (kt) * AKB;                                                    \
        const uint32_t _kb = sb + (buf) * (64 * ASTR * 4);                             \
        _Pragma("unroll")                                                              \
        for (int _i = 0; _i < 8; _i++) {                                               \
            const int _f4 = tid + _i * 128;                                            \
            const int _j = _f4 >> 4;                                                   \
            const int _dc = (_f4 & 15) << 2;                                           \
            cpa16(_kb + (_j * ASTR + _dc) * 4, kbase + (size_t)(_j0 + _j) * D_ + _dc); \
        }                                                                              \
        CP_COMMIT();                                                                   \
    } while (0)

    // Prologue: tile 0
    LOADK(0, 0);
    {
        uint32_t* Vt = sm + 2 * 64 * ASTR;   // buf 0
#pragma unroll
        for (int i = 0; i < 8; i++) {
            const int v4 = tid + i * 128;
            const int j = v4 & 63;
            const int dg = v4 >> 6;
            uint4 vv = *(const uint4*)(vbase + (size_t)j * D_ + dg * 4);
            Vt[(dg * 4 + 0) * ASTR + j] = vv.x;
            Vt[(dg * 4 + 1) * ASTR + j] = vv.y;
            Vt[(dg * 4 + 2) * ASTR + j] = vv.z;
            Vt[(dg * 4 + 3) * ASTR + j] = vv.w;
        }
    }

    const int ntiles = qb + 1;
#pragma unroll 1
    for (int kt = 0; kt < ntiles; kt++) {
        const int j0 = kt * AKB;
        const int buf = kt & 1;

        // Prefetch next tile's V into registers (overlaps the K wait)
        uint4 vr[8];
        if (kt + 1 < ntiles) {
#pragma unroll
            for (int i = 0; i < 8; i++) {
                const int v4 = tid + i * 128;
                const int j = v4 & 63;
                const int dg = v4 >> 6;
                vr[i] = *(const uint4*)(vbase + (size_t)(j0 + AKB + j) * D_ + dg * 4);
            }
        }

        CP_WAIT(0);          // K(kt) landed
        __syncthreads();     // everyone done with buffers of tile kt-1

        if (kt + 1 < ntiles) {
            LOADK(kt + 1, buf ^ 1);
            uint32_t* Vt = sm + (2 + (buf ^ 1)) * 64 * ASTR;
#pragma unroll
            for (int i = 0; i < 8; i++) {
                const int v4 = tid + i * 128;
                const int j = v4 & 63;
                const int dg = v4 >> 6;
                Vt[(dg * 4 + 0) * ASTR + j] = vr[i].x;
                Vt[(dg * 4 + 1) * ASTR + j] = vr[i].y;
                Vt[(dg * 4 + 2) * ASTR + j] = vr[i].z;
                Vt[(dg * 4 + 3) * ASTR + j] = vr[i].w;
            }
        }

        const uint32_t Ksb = sb + buf * (64 * ASTR * 4);
        const uint32_t Vtb = sb + (2 + buf) * (64 * ASTR * 4);

        // ---- S = Q K^T ----
        float s[8][4];
#pragma unroll
        for (int jn = 0; jn < 8; jn++)
#pragma unroll
            for (int v = 0; v < 4; v++) s[jn][v] = 0.0f;
#pragma unroll
        for (int kc = 0; kc < 8; kc++) {
            uint32_t bb[4][4];
#pragma unroll
            for (int p = 0; p < 4; p++)
                ldmx4(bb[p], Ksb + nkoff + p * (16 * ASTR * 4) + kc * 32);
#pragma unroll
            for (int jn = 0; jn < 8; jn++)
                mma_tf32(s[jn], qf[kc], &bb[jn >> 1][(jn & 1) * 2]);
        }

        // scale + causal mask (only the diagonal tile crosses rows)
        const bool masked = (kt == ntiles - 1);
#pragma unroll
        for (int jn = 0; jn < 8; jn++) {
            s[jn][0] *= SCL2E; s[jn][1] *= SCL2E;
            s[jn][2] *= SCL2E; s[jn][3] *= SCL2E;
            if (masked) {
                const int c0m = j0 + jn * 8 + 2 * tig;
                if (c0m > r1) s[jn][0] = __int_as_float(0xff800000);
                if (c0m + 1 > r1) s[jn][1] = __int_as_float(0xff800000);
                if (c0m > r2) s[jn][2] = __int_as_float(0xff800000);
                if (c0m + 1 > r2) s[jn][3] = __int_as_float(0xff800000);
            }
        }

        // ---- online softmax (log2 domain); p kept in s registers ----
        float nm1 = m1, nm2 = m2;
#pragma unroll
        for (int jn = 0; jn < 8; jn++) {
            nm1 = fmaxf(nm1, fmaxf(s[jn][0], s[jn][1]));
            nm2 = fmaxf(nm2, fmaxf(s[jn][2], s[jn][3]));
        }
        nm1 = fmaxf(nm1, __shfl_xor_sync(0xffffffffu, nm1, 1));
        nm1 = fmaxf(nm1, __shfl_xor_sync(0xffffffffu, nm1, 2));
        nm2 = fmaxf(nm2, __shfl_xor_sync(0xffffffffu, nm2, 1));
        nm2 = fmaxf(nm2, __shfl_xor_sync(0xffffffffu, nm2, 2));

        const float corr1 = ex2(m1 - nm1);
        const float corr2 = ex2(m2 - nm2);
        m1 = nm1; m2 = nm2;

        float ls1 = 0.0f, ls2 = 0.0f;
#pragma unroll
        for (int jn = 0; jn < 8; jn++) {
            s[jn][0] = ex2(s[jn][0] - nm1);
            s[jn][1] = ex2(s[jn][1] - nm1);
            s[jn][2] = ex2(s[jn][2] - nm2);
            s[jn][3] = ex2(s[jn][3] - nm2);
            ls1 += s[jn][0] + s[jn][1];
            ls2 += s[jn][2] + s[jn][3];
        }
        ls1 += __shfl_xor_sync(0xffffffffu, ls1, 1);
        ls1 += __shfl_xor_sync(0xffffffffu, ls1, 2);
        ls2 += __shfl_xor_sync(0xffffffffu, ls2, 1);
        ls2 += __shfl_xor_sync(0xffffffffu, ls2, 2);
        l1 = l1 * corr1 + ls1;
        l2 = l2 * corr2 + ls2;

#pragma unroll
        for (int dn = 0; dn < 8; dn++) {
            o[dn][0] *= corr1; o[dn][1] *= corr1;
            o[dn][2] *= corr2; o[dn][3] *= corr2;
        }

        // ---- O += P V, P fragments built by quad shuffles (no smem) ----
        // P[r][8kc+c] lives at quad-lane (c>>1), slot (c&1).
        const int srcA = (lane & ~3) | (tig >> 1);
        const int srcB = srcA | 2;
#pragma unroll
        for (int kc = 0; kc < 8; kc++) {
            const float a00 = __shfl_sync(0xffffffffu, s[kc][0], srcA);
            const float a01 = __shfl_sync(0xffffffffu, s[kc][1], srcA);
            const float a10 = __shfl_sync(0xffffffffu, s[kc][2], srcA);
            const float a11 = __shfl_sync(0xffffffffu, s[kc][3], srcA);
            const float b00 = __shfl_sync(0xffffffffu, s[kc][0], srcB);
            const float b01 = __shfl_sync(0xffffffffu, s[kc][1], srcB);
            const float b10 = __shfl_sync(0xffffffffu, s[kc][2], srcB);
            const float b11 = __shfl_sync(0xffffffffu, s[kc][3], srcB);
            uint32_t pf[4];
            const bool oddc = (tig & 1);
            pf[0] = tf32u(oddc ? a01 : a00);   // P[r1][8kc+tig]
            pf[1] = tf32u(oddc ? a11 : a10);   // P[r2][8kc+tig]
            pf[2] = tf32u(oddc ? b01 : b00);   // P[r1][8kc+tig+4]
            pf[3] = tf32u(oddc ? b11 : b10);   // P[r2][8kc+tig+4]

            uint32_t vb[4][4];
#pragma unroll
            for (int p = 0; p < 4; p++)
                ldmx4(vb[p], Vtb + nkoff + p * (16 * ASTR * 4) + kc * 32);
#pragma unroll
            for (int dn = 0; dn < 8; dn++)
                mma_tf32(o[dn], pf, &vb[dn >> 1][(dn & 1) * 2]);
        }
    }
#undef LOADK

    // ---- write normalized output (rounded for proj GEMM), [B*T, E] ----
    const float inv1 = 1.0f / l1;
    const float inv2 = 1.0f / l2;
    const int b = bh / H_;
    const int h = bh - b * H_;
    uint32_t* o1 = (uint32_t*)(g_att) + ((size_t)(b * T_ + r1)) * E_ + h * D_;
    uint32_t* o2 = (uint32_t*)(g_att) + ((size_t)(b * T_ + r2)) * E_ + h * D_;
#pragma unroll
    for (int dn = 0; dn < 8; dn++) {
        const int d = dn * 8 + 2 * tig;
        *(uint2*)(o1 + d) = make_uint2(tf32u(o[dn][0] * inv1), tf32u(o[dn][1] * inv1));
        *(uint2*)(o2 + d) = make_uint2(tf32u(o[dn][2] * inv2), tf32u(o[dn][3] * inv2));
    }
}

// ---------------------------------------------------------------------------
// Launch
// ---------------------------------------------------------------------------
extern "C" void kernel_launch(void* const* d_in, const int* in_sizes, int n_in,
                              void* d_out, int out_size) {
    const float* x = (const float*)d_in[0];       // [B,T,E]
    const float* w_qkv = (const float*)d_in[1];   // [3E,E]
    const float* w_proj = (const float*)d_in[2];  // [E,E]
    float* out = (float*)d_out;                   // [B,T,E]

    static bool attr_done = false;
    if (!attr_done) {
        cudaFuncSetAttribute(mma_gemm<0, 3 * E_, E_, 128>,
                             cudaFuncAttributeMaxDynamicSharedMemorySize, GSMEM128);
        cudaFuncSetAttribute(mma_gemm<1, E_, E_, 64>,
                             cudaFuncAttributeMaxDynamicSharedMemorySize, GSMEM64);
        cudaFuncSetAttribute(attn_mma, cudaFuncAttributeMaxDynamicSharedMemorySize, ASMEM);
        attr_done = true;
    }

    float *xr, *wqkvr, *wprojr, *attp;
    cudaGetSymbolAddress((void**)&xr, g_xr);
    cudaGetSymbolAddress((void**)&wqkvr, g_wqkvr);
    cudaGetSymbolAddress((void**)&wprojr, g_wprojr);
    cudaGetSymbolAddress((void**)&attp, g_att);

    // 0) Rounding prep (tf32 RNA), one launch
    round_all<<<8192, 256>>>(x, w_qkv, w_proj);

    // 1) QKV projection -> rounded q/k/v in [B,H,T,D]   (grid 24 x 32)
    mma_gemm<0, 3 * E_, E_, 128><<<dim3(3 * E_ / 128, BT_ / 128), 128, GSMEM128>>>(xr, wqkvr, nullptr);

    // 2) Causal flash attention -> rounded g_att [B*T, E]   (grid 32 x 32)
    attn_mma<<<dim3(T_ / AQB, B_ * H_), 128, ASMEM>>>();

    // 3) Output projection -> d_out (fp32)   (grid 8 x 64)
    mma_gemm<1, E_, E_, 64><<<dim3(E_ / 128, BT_ / 64), 64, GSMEM64>>>(attp, wprojr, out);
}

// round 12
// speedup vs baseline: 1.4572x; 1.4572x over previous
#include <cuda_runtime.h>
#include <cstdint>

// Problem constants
#define B_ 2
#define T_ 2048
#define E_ 1024
#define H_ 16
#define D_ 64
#define BT_ (B_ * T_)

// Scratch (allocation-free: __device__ globals). All tf32-valued fp32 bits.
__device__ float g_q[(size_t)B_ * H_ * T_ * D_];
__device__ float g_k[(size_t)B_ * H_ * T_ * D_];
__device__ float g_v[(size_t)B_ * H_ * T_ * D_];
__device__ float g_att[(size_t)BT_ * E_];
__device__ float g_xr[(size_t)BT_ * E_];
__device__ float g_wqkvr[(size_t)3 * E_ * E_];
__device__ float g_wprojr[(size_t)E_ * E_];

// ---------------------------------------------------------------------------
__device__ __forceinline__ uint32_t smem_u32(const void* p) {
    uint32_t a;
    asm("{ .reg .u64 t; cvta.to.shared.u64 t, %1; cvt.u32.u64 %0, t; }" : "=r"(a) : "l"(p));
    return a;
}
__device__ __forceinline__ uint32_t tf32u(float x) {
    uint32_t r;
    asm("cvt.rna.tf32.f32 %0, %1;" : "=r"(r) : "f"(x));
    return r;
}
__device__ __forceinline__ float ex2(float x) {
    float r;
    asm("ex2.approx.f32 %0, %1;" : "=f"(r) : "f"(x));
    return r;
}
__device__ __forceinline__ void mma_tf32(float* c, const uint32_t* a, const uint32_t* b) {
    asm volatile(
        "mma.sync.aligned.m16n8k8.row.col.f32.tf32.tf32.f32 "
        "{%0,%1,%2,%3}, {%4,%5,%6,%7}, {%8,%9}, {%0,%1,%2,%3};"
        : "+f"(c[0]), "+f"(c[1]), "+f"(c[2]), "+f"(c[3])
        : "r"(a[0]), "r"(a[1]), "r"(a[2]), "r"(a[3]), "r"(b[0]), "r"(b[1]));
}
__device__ __forceinline__ void ldmx4(uint32_t* r, uint32_t a) {
    asm volatile("ldmatrix.sync.aligned.m8n8.x4.shared.b16 {%0,%1,%2,%3}, [%4];"
                 : "=r"(r[0]), "=r"(r[1]), "=r"(r[2]), "=r"(r[3]) : "r"(a));
}
__device__ __forceinline__ void cpa16(uint32_t s, const void* g) {
    asm volatile("cp.async.cg.shared.global [%0], [%1], 16;" :: "r"(s), "l"(g) : "memory");
}
#define CP_COMMIT() asm volatile("cp.async.commit_group;" ::: "memory")
#define CP_WAIT(n) asm volatile("cp.async.wait_group %0;" :: "n"(n) : "memory")

// ---------------------------------------------------------------------------
// Prep: one kernel rounds x, w_qkv, w_proj to tf32 (RNA). f4 segments:
// x: [0, 1048576), wqkv: [1048576, 1835008), wproj: [1835008, 2097152)
// ---------------------------------------------------------------------------
__global__ void __launch_bounds__(256) round_all(const float* __restrict__ x,
                                                 const float* __restrict__ wq,
                                                 const float* __restrict__ wp) {
    const size_t f4 = (size_t)blockIdx.x * 256 + threadIdx.x;
    const float* src;
    float* dst;
    size_t off;
    if (f4 < 1048576) { src = x; dst = g_xr; off = f4; }
    else if (f4 < 1835008) { src = wq; dst = g_wqkvr; off = f4 - 1048576; }
    else { src = wp; dst = g_wprojr; off = f4 - 1835008; }
    const size_t i = off * 4;
    float4 v = *(const float4*)(src + i);
    *(uint4*)(dst + i) = make_uint4(tf32u(v.x), tf32u(v.y), tf32u(v.z), tf32u(v.w));
}

// ---------------------------------------------------------------------------
// TF32 mma.sync GEMM. BMt x 128 CTA tile, THREADS = BMt threads
// (BMt/64 x 2 warps, warp tile 64x64). BK=32, 2-stage cp.async, ldmatrix.
// C[m,n] = sum_k A[m,k] * Bm[n,k]; A,B pre-rounded tf32 bits.
// MODE 0: scatter rounded into g_q/g_k/g_v. MODE 1: fp32 store to C.
// BMt=256 halves B-matrix re-reads (L2-BW-bound case: QKV).
// ---------------------------------------------------------------------------
#define BK 32
#define LDPG 36                       // u32 row stride (144B), conflict-free

template <int MODE, int Ntot, int Ktot, int BMt>
__global__ void __launch_bounds__(BMt) mma_gemm(const float* __restrict__ A,
                                                const float* __restrict__ Bm,
                                                float* __restrict__ C) {
    constexpr int THREADS = BMt;
    constexpr int NWM = BMt / 64;
    constexpr int STG_A = BMt * LDPG;     // u32
    constexpr int STG_B = 128 * LDPG;     // u32
    constexpr int STAGE = STG_A + STG_B;  // u32

    extern __shared__ uint32_t sm[];
    const uint32_t sb = smem_u32(sm);

    const int tid = threadIdx.x;
    const int lane = tid & 31;
    const int wid = tid >> 5;
    const int gid = lane >> 2;
    const int tig = lane & 3;
    const int wm = (wid % NWM) * 64;
    const int wn = (wid / NWM) * 64;
    const int m0 = blockIdx.y * BMt;
    const int n0 = blockIdx.x * 128;

    // Fragment base byte-offsets within a stage (ldmatrix lane mapping)
    const uint32_t aoff = ((wm + (lane & 15)) * LDPG + ((lane & 16) >> 2)) * 4;
    const uint32_t boff = ((wn + ((lane & 16) >> 1) + (lane & 7)) * LDPG + ((lane & 8) >> 1)) * 4;

    float acc[4][8][4];
#pragma unroll
    for (int i = 0; i < 4; i++)
#pragma unroll
        for (int j = 0; j < 8; j++)
#pragma unroll
            for (int v = 0; v < 4; v++) acc[i][j][v] = 0.0f;

#define ISSUE(g)                                                                       \
    do {                                                                               \
        const int _k0 = (g) * BK;                                                      \
        const uint32_t _sa = sb + ((g) & 1) * (STAGE * 4);                             \
        const uint32_t _sb2 = _sa + STG_A * 4;                                         \
        _Pragma("unroll")                                                              \
        for (int _i = 0; _i < 8; _i++) {                                               \
            const int _id = tid + _i * THREADS;                                        \
            const int _r = _id >> 3;                                                   \
            const int _c = (_id & 7) << 2;                                             \
            cpa16(_sa + (_r * LDPG + _c) * 4, A + (size_t)(m0 + _r) * Ktot + _k0 + _c); \
        }                                                                              \
        _Pragma("unroll")                                                              \
        for (int _i = 0; _i < 1024 / THREADS; _i++) {                                  \
            const int _id = tid + _i * THREADS;                                        \
            const int _r = _id >> 3;                                                   \
            const int _c = (_id & 7) << 2;                                             \
            cpa16(_sb2 + (_r * LDPG + _c) * 4, Bm + (size_t)(n0 + _r) * Ktot + _k0 + _c); \
        }                                                                              \
        CP_COMMIT();                                                                   \
    } while (0)

    ISSUE(0);

    const int NITER = Ktot / BK;
#pragma unroll 1
    for (int it = 0; it < NITER; ++it) {
        CP_WAIT(0);
        __syncthreads();
        if (it + 1 < NITER) ISSUE(it + 1);

        const uint32_t stg = sb + (it & 1) * (STAGE * 4);
        const uint32_t ab = stg + aoff;
        const uint32_t bbv = stg + STG_A * 4 + boff;

#pragma unroll
        for (int kc = 0; kc < 4; kc++) {
            uint32_t af[4][4], bb[4][4];
#pragma unroll
            for (int mi = 0; mi < 4; mi++)
                ldmx4(af[mi], ab + mi * (16 * LDPG * 4) + kc * 32);
#pragma unroll
            for (int p = 0; p < 4; p++)
                ldmx4(bb[p], bbv + p * (16 * LDPG * 4) + kc * 32);
#pragma unroll
            for (int mi = 0; mi < 4; mi++)
#pragma unroll
                for (int ni = 0; ni < 8; ni++)
                    mma_tf32(acc[mi][ni], af[mi], &bb[ni >> 1][(ni & 1) * 2]);
        }
    }
#undef ISSUE

    // Epilogue
#pragma unroll
    for (int mi = 0; mi < 4; mi++) {
#pragma unroll
        for (int ni = 0; ni < 8; ni++) {
            const int m = m0 + wm + mi * 16 + gid;
            const int n = n0 + wn + ni * 8 + 2 * tig;
            if (MODE == 0) {
                const int which = n >> 10;
                const int e = n & (E_ - 1);
                const int h = e >> 6;
                const int d = e & 63;
                float* base = (which == 0) ? g_q : (which == 1) ? g_k : g_v;
#pragma unroll
                for (int rr = 0; rr < 2; rr++) {
                    const int mm = m + rr * 8;
                    const int b = mm >> 11;
                    const int t = mm & (T_ - 1);
                    uint2 o = make_uint2(tf32u(acc[mi][ni][2 * rr]),
                                         tf32u(acc[mi][ni][2 * rr + 1]));
                    *(uint2*)((uint32_t*)base + (((size_t)(b * H_ + h) * T_ + t) * D_ + d)) = o;
                }
            } else {
#pragma unroll
                for (int rr = 0; rr < 2; rr++) {
                    const int mm = m + rr * 8;
                    *(float2*)(C + (size_t)mm * Ntot + n) =
                        make_float2(acc[mi][ni][2 * rr], acc[mi][ni][2 * rr + 1]);
                }
            }
        }
    }
}

#define GSMEM_QKV (2 * (256 * LDPG + 128 * LDPG) * 4)   // 110592
#define GSMEM_PRJ (2 * (128 * LDPG + 128 * LDPG) * 4)   // 73728

// ---------------------------------------------------------------------------
// TF32 mma.sync causal flash attention (R10 configuration — proven best).
// Block: 128 q-rows x 1 head, 256 threads (8 warps x 16 rows). K-tile 64.
// Double-buffered Ks/Vt, P via per-warp smem. One __syncthreads per tile.
// ---------------------------------------------------------------------------
#define ASTR 68
#define AQB 128
#define AKB 64
#define SCL2E 0.18033688011112042f   // (1/8) * log2(e)
#define ASMEM ((4 * 64 * ASTR + 8 * 16 * ASTR) * 4)

__global__ void __launch_bounds__(256) attn_mma() {
    extern __shared__ uint32_t sm[];
    const uint32_t sb = smem_u32(sm);

    const int tid = threadIdx.x;
    const int wid = tid >> 5;
    const int lane = tid & 31;
    const int gid = lane >> 2;
    const int tig = lane & 3;

    const int bh = blockIdx.y;
    const int qb = gridDim.x - 1 - blockIdx.x;   // heavy blocks first
    const int q0 = qb * AQB;
    const int wq = wid * 16;
    const int r1 = q0 + wq + gid;
    const int r2 = r1 + 8;

    const uint32_t Pwb = sb + (4 * 64 * ASTR + wid * 16 * ASTR) * 4;

    // ldmatrix fragment byte-offsets (within a K/Vt buffer)
    const uint32_t nkoff = ((((lane & 16) >> 1) + (lane & 7)) * ASTR + ((lane & 8) >> 1)) * 4;
    const uint32_t pfoff = ((lane & 15) * ASTR + ((lane & 16) >> 2)) * 4;

    const uint32_t* kbase = (const uint32_t*)(g_k + (size_t)bh * T_ * D_);
    const uint32_t* vbase = (const uint32_t*)(g_v + (size_t)bh * T_ * D_);

    // Q fragments (pre-rounded bits, held for whole block)
    uint32_t qf[8][4];
    {
        const uint32_t* q1 = (const uint32_t*)(g_q) + ((size_t)bh * T_ + r1) * D_;
        const uint32_t* q2 = (const uint32_t*)(g_q) + ((size_t)bh * T_ + r2) * D_;
#pragma unroll
        for (int kc = 0; kc < 8; kc++) {
            qf[kc][0] = q1[kc * 8 + tig];
            qf[kc][1] = q2[kc * 8 + tig];
            qf[kc][2] = q1[kc * 8 + tig + 4];
            qf[kc][3] = q2[kc * 8 + tig + 4];
        }
    }

    float o[8][4];
#pragma unroll
    for (int i = 0; i < 8; i++)
#pragma unroll
        for (int v = 0; v < 4; v++) o[i][v] = 0.0f;
    float m1 = __int_as_float(0xff800000), m2 = __int_as_float(0xff800000);
    float l1 = 0.0f, l2 = 0.0f;

#define LOADK(kt, buf)                                                                 \
    do {                                                                               \
        const int _j0 = (kt) * AKB;                                                    \
        const uint32_t _kb = sb + (buf) * (64 * ASTR * 4);                             \
        _Pragma("unroll")                                                              \
        for (int _i = 0; _i < 4; _i++) {                                               \
            const int _f4 = tid + _i * 256;                                            \
            const int _j = _f4 >> 4;                                                   \
            const int _dc = (_f4 & 15) << 2;                                           \
            cpa16(_kb + (_j * ASTR + _dc) * 4, kbase + (size_t)(_j0 + _j) * D_ + _dc); \
        }                                                                              \
        CP_COMMIT();                                                                   \
    } while (0)

    // Prologue: tile 0
    LOADK(0, 0);
    {
        uint32_t* Vt = sm + 2 * 64 * ASTR;   // buf 0
#pragma unroll
        for (int i = 0; i < 4; i++) {
            const int v4 = tid + i * 256;
            const int j = v4 & 63;
            const int dg = v4 >> 6;
            uint4 vv = *(const uint4*)(vbase + (size_t)j * D_ + dg * 4);
            Vt[(dg * 4 + 0) * ASTR + j] = vv.x;
            Vt[(dg * 4 + 1) * ASTR + j] = vv.y;
            Vt[(dg * 4 + 2) * ASTR + j] = vv.z;
            Vt[(dg * 4 + 3) * ASTR + j] = vv.w;
        }
    }

    const int ntiles = (q0 + AQB) / AKB;
#pragma unroll 1
    for (int kt = 0; kt < ntiles; kt++) {
        const int j0 = kt * AKB;
        const int buf = kt & 1;

        // Prefetch next tile's V into registers (overlaps the K wait)
        uint4 vr[4];
        if (kt + 1 < ntiles) {
#pragma unroll
            for (int i = 0; i < 4; i++) {
                const int v4 = tid + i * 256;
                const int j = v4 & 63;
                const int dg = v4 >> 6;
                vr[i] = *(const uint4*)(vbase + (size_t)(j0 + AKB + j) * D_ + dg * 4);
            }
        }

        CP_WAIT(0);          // K(kt) landed
        __syncthreads();     // everyone done with buffers of tile kt-1

        if (kt + 1 < ntiles) {
            LOADK(kt + 1, buf ^ 1);
            uint32_t* Vt = sm + (2 + (buf ^ 1)) * 64 * ASTR;
#pragma unroll
            for (int i = 0; i < 4; i++) {
                const int v4 = tid + i * 256;
                const int j = v4 & 63;
                const int dg = v4 >> 6;
                Vt[(dg * 4 + 0) * ASTR + j] = vr[i].x;
                Vt[(dg * 4 + 1) * ASTR + j] = vr[i].y;
                Vt[(dg * 4 + 2) * ASTR + j] = vr[i].z;
                Vt[(dg * 4 + 3) * ASTR + j] = vr[i].w;
            }
        }

        if (j0 <= q0 + wq + 15) {
            const uint32_t Ksb = sb + buf * (64 * ASTR * 4);
            const uint32_t Vtb = sb + (2 + buf) * (64 * ASTR * 4);

            // ---- S = Q K^T ----
            float s[8][4];
#pragma unroll
            for (int jn = 0; jn < 8; jn++)
#pragma unroll
                for (int v = 0; v < 4; v++) s[jn][v] = 0.0f;
#pragma unroll
            for (int kc = 0; kc < 8; kc++) {
                uint32_t bb[4][4];
#pragma unroll
                for (int p = 0; p < 4; p++)
                    ldmx4(bb[p], Ksb + nkoff + p * (16 * ASTR * 4) + kc * 32);
#pragma unroll
                for (int jn = 0; jn < 8; jn++)
                    mma_tf32(s[jn], qf[kc], &bb[jn >> 1][(jn & 1) * 2]);
            }

            // scale + causal mask
            const bool masked = (kt >= ntiles - 2);
#pragma unroll
            for (int jn = 0; jn < 8; jn++) {
                s[jn][0] *= SCL2E; s[jn][1] *= SCL2E;
                s[jn][2] *= SCL2E; s[jn][3] *= SCL2E;
                if (masked) {
                    const int c0m = j0 + jn * 8 + 2 * tig;
                    if (c0m > r1) s[jn][0] = __int_as_float(0xff800000);
                    if (c0m + 1 > r1) s[jn][1] = __int_as_float(0xff800000);
                    if (c0m > r2) s[jn][2] = __int_as_float(0xff800000);
                    if (c0m + 1 > r2) s[jn][3] = __int_as_float(0xff800000);
                }
            }

            // ---- online softmax (log2 domain) ----
            float nm1 = m1, nm2 = m2;
#pragma unroll
            for (int jn = 0; jn < 8; jn++) {
                nm1 = fmaxf(nm1, fmaxf(s[jn][0], s[jn][1]));
                nm2 = fmaxf(nm2, fmaxf(s[jn][2], s[jn][3]));
            }
            nm1 = fmaxf(nm1, __shfl_xor_sync(0xffffffffu, nm1, 1));
            nm1 = fmaxf(nm1, __shfl_xor_sync(0xffffffffu, nm1, 2));
            nm2 = fmaxf(nm2, __shfl_xor_sync(0xffffffffu, nm2, 1));
            nm2 = fmaxf(nm2, __shfl_xor_sync(0xffffffffu, nm2, 2));

            const float corr1 = ex2(m1 - nm1);
            const float corr2 = ex2(m2 - nm2);
            m1 = nm1; m2 = nm2;

            float ls1 = 0.0f, ls2 = 0.0f;
            uint32_t* Pw = sm + 4 * 64 * ASTR + wid * 16 * ASTR;
#pragma unroll
            for (int jn = 0; jn < 8; jn++) {
                float p0 = ex2(s[jn][0] - nm1);
                float p1 = ex2(s[jn][1] - nm1);
                float p2 = ex2(s[jn][2] - nm2);
                float p3 = ex2(s[jn][3] - nm2);
                ls1 += p0 + p1;
                ls2 += p2 + p3;
                const int cw = jn * 8 + 2 * tig;
                *(uint2*)&Pw[gid * ASTR + cw] = make_uint2(tf32u(p0), tf32u(p1));
                *(uint2*)&Pw[(gid + 8) * ASTR + cw] = make_uint2(tf32u(p2), tf32u(p3));
            }
            ls1 += __shfl_xor_sync(0xffffffffu, ls1, 1);
            ls1 += __shfl_xor_sync(0xffffffffu, ls1, 2);
            ls2 += __shfl_xor_sync(0xffffffffu, ls2, 1);
            ls2 += __shfl_xor_sync(0xffffffffu, ls2, 2);
            l1 = l1 * corr1 + ls1;
            l2 = l2 * corr2 + ls2;

#pragma unroll
            for (int dn = 0; dn < 8; dn++) {
                o[dn][0] *= corr1; o[dn][1] *= corr1;
                o[dn][2] *= corr2; o[dn][3] *= corr2;
            }
            __syncwarp();

            // ---- O += P V ----
#pragma unroll
            for (int kc = 0; kc < 8; kc++) {
                uint32_t pf[4], vb[4][4];
                ldmx4(pf, Pwb + pfoff + kc * 32);
#pragma unroll
                for (int p = 0; p < 4; p++)
                    ldmx4(vb[p], Vtb + nkoff + p * (16 * ASTR * 4) + kc * 32);
#pragma unroll
                for (int dn = 0; dn < 8; dn++)
                    mma_tf32(o[dn], pf, &vb[dn >> 1][(dn & 1) * 2]);
            }
        }
    }
#undef LOADK

    // ---- write normalized output (rounded for proj GEMM), [B*T, E] ----
    const float inv1 = 1.0f / l1;
    const float inv2 = 1.0f / l2;
    const int b = bh / H_;
    const int h = bh - b * H_;
    uint32_t* o1 = (uint32_t*)(g_att) + ((size_t)(b * T_ + r1)) * E_ + h * D_;
    uint32_t* o2 = (uint32_t*)(g_att) + ((size_t)(b * T_ + r2)) * E_ + h * D_;
#pragma unroll
    for (int dn = 0; dn < 8; dn++) {
        const int d = dn * 8 + 2 * tig;
        *(uint2*)(o1 + d) = make_uint2(tf32u(o[dn][0] * inv1), tf32u(o[dn][1] * inv1));
        *(uint2*)(o2 + d) = make_uint2(tf32u(o[dn][2] * inv2), tf32u(o[dn][3] * inv2));
    }
}

// ---------------------------------------------------------------------------
// Launch
// ---------------------------------------------------------------------------
extern "C" void kernel_launch(void* const* d_in, const int* in_sizes, int n_in,
                              void* d_out, int out_size) {
    const float* x = (const float*)d_in[0];       // [B,T,E]
    const float* w_qkv = (const float*)d_in[1];   // [3E,E]
    const float* w_proj = (const float*)d_in[2];  // [E,E]
    float* out = (float*)d_out;                   // [B,T,E]

    static bool attr_done = false;
    if (!attr_done) {
        cudaFuncSetAttribute(mma_gemm<0, 3 * E_, E_, 256>,
                             cudaFuncAttributeMaxDynamicSharedMemorySize, GSMEM_QKV);
        cudaFuncSetAttribute(mma_gemm<1, E_, E_, 128>,
                             cudaFuncAttributeMaxDynamicSharedMemorySize, GSMEM_PRJ);
        cudaFuncSetAttribute(attn_mma, cudaFuncAttributeMaxDynamicSharedMemorySize, ASMEM);
        attr_done = true;
    }

    float *xr, *wqkvr, *wprojr, *attp;
    cudaGetSymbolAddress((void**)&xr, g_xr);
    cudaGetSymbolAddress((void**)&wqkvr, g_wqkvr);
    cudaGetSymbolAddress((void**)&wprojr, g_wprojr);
    cudaGetSymbolAddress((void**)&attp, g_att);

    // 0) Rounding prep (tf32 RNA), one launch
    round_all<<<8192, 256>>>(x, w_qkv, w_proj);

    // 1) QKV projection -> rounded q/k/v in [B,H,T,D]   (grid 24 x 16, 256 thr)
    mma_gemm<0, 3 * E_, E_, 256><<<dim3(3 * E_ / 128, BT_ / 256), 256, GSMEM_QKV>>>(xr, wqkvr, nullptr);

    // 2) Causal flash attention -> rounded g_att [B*T, E]   (grid 16 x 32)
    attn_mma<<<dim3(T_ / AQB, B_ * H_), 256, ASMEM>>>();

    // 3) Output projection -> d_out (fp32)   (grid 8 x 32, 128 thr)
    mma_gemm<1, E_, E_, 128><<<dim3(E_ / 128, BT_ / 128), 128, GSMEM_PRJ>>>(attp, wprojr, out);
}

// round 14
// speedup vs baseline: 2.7384x; 1.8792x over previous
#include <cuda_runtime.h>
#include <cuda_fp16.h>
#include <cstdint>

// Problem constants
#define B_ 2
#define T_ 2048
#define E_ 1024
#define H_ 16
#define D_ 64
#define BT_ (B_ * T_)

// Scratch (allocation-free: __device__ globals). fp16 operand copies.
__device__ __half g_q[(size_t)B_ * H_ * T_ * D_];
__device__ __half g_k[(size_t)B_ * H_ * T_ * D_];
__device__ __half g_v[(size_t)B_ * H_ * T_ * D_];
__device__ __half g_att[(size_t)BT_ * E_];
__device__ __half g_xr[(size_t)BT_ * E_];
__device__ __half g_wqkvr[(size_t)3 * E_ * E_];
__device__ __half g_wprojr[(size_t)E_ * E_];

// ---------------------------------------------------------------------------
__device__ __forceinline__ uint32_t smem_u32(const void* p) {
    uint32_t a;
    asm("{ .reg .u64 t; cvta.to.shared.u64 t, %1; cvt.u32.u64 %0, t; }" : "=r"(a) : "l"(p));
    return a;
}
__device__ __forceinline__ float ex2(float x) {
    float r;
    asm("ex2.approx.f32 %0, %1;" : "=f"(r) : "f"(x));
    return r;
}
// pack two floats -> half2 bits (lo, hi), round-to-nearest
__device__ __forceinline__ uint32_t h2u(float lo, float hi) {
    uint32_t r;
    asm("cvt.rn.f16x2.f32 %0, %1, %2;" : "=r"(r) : "f"(hi), "f"(lo));
    return r;
}
// D(16x8,f32) += A(16x16,f16) * B(16x8,f16)   (row.col)
__device__ __forceinline__ void mma_f16(float* c, const uint32_t* a, const uint32_t* b) {
    asm volatile(
        "mma.sync.aligned.m16n8k16.row.col.f32.f16.f16.f32 "
        "{%0,%1,%2,%3}, {%4,%5,%6,%7}, {%8,%9}, {%0,%1,%2,%3};"
        : "+f"(c[0]), "+f"(c[1]), "+f"(c[2]), "+f"(c[3])
        : "r"(a[0]), "r"(a[1]), "r"(a[2]), "r"(a[3]), "r"(b[0]), "r"(b[1]));
}
__device__ __forceinline__ void ldmx4(uint32_t* r, uint32_t a) {
    asm volatile("ldmatrix.sync.aligned.m8n8.x4.shared.b16 {%0,%1,%2,%3}, [%4];"
                 : "=r"(r[0]), "=r"(r[1]), "=r"(r[2]), "=r"(r[3]) : "r"(a));
}
__device__ __forceinline__ void ldmx4t(uint32_t* r, uint32_t a) {
    asm volatile("ldmatrix.sync.aligned.m8n8.x4.trans.shared.b16 {%0,%1,%2,%3}, [%4];"
                 : "=r"(r[0]), "=r"(r[1]), "=r"(r[2]), "=r"(r[3]) : "r"(a));
}
__device__ __forceinline__ void cpa16(uint32_t s, const void* g) {
    asm volatile("cp.async.cg.shared.global [%0], [%1], 16;" :: "r"(s), "l"(g) : "memory");
}
#define CP_COMMIT() asm volatile("cp.async.commit_group;" ::: "memory")
#define CP_WAIT(n) asm volatile("cp.async.wait_group %0;" :: "n"(n) : "memory")

// ---------------------------------------------------------------------------
// Prep: round x, w_qkv, w_proj to fp16 (RN). f4 segments:
// x: [0, 1048576), wqkv: [1048576, 1835008), wproj: [1835008, 2097152)
// ---------------------------------------------------------------------------
__global__ void __launch_bounds__(256) round_all(const float* __restrict__ x,
                                                 const float* __restrict__ wq,
                                                 const float* __restrict__ wp) {
    const size_t f4 = (size_t)blockIdx.x * 256 + threadIdx.x;
    const float* src;
    __half* dst;
    size_t off;
    if (f4 < 1048576) { src = x; dst = g_xr; off = f4; }
    else if (f4 < 1835008) { src = wq; dst = g_wqkvr; off = f4 - 1048576; }
    else { src = wp; dst = g_wprojr; off = f4 - 1835008; }
    const size_t i = off * 4;
    float4 v = *(const float4*)(src + i);
    *(uint2*)(dst + i) = make_uint2(h2u(v.x, v.y), h2u(v.z, v.w));
}

// ---------------------------------------------------------------------------
// FP16 mma.sync GEMM (m16n8k16). 128x128 CTA tile, 128 threads
// (2x2 warps, warp tile 64x64). BK=32, 2-stage cp.async, ldmatrix b16.
// C[m,n] = sum_k A[m,k] * Bm[n,k]; A,B fp16.
// MODE 0: store fp16 into g_q/g_k/g_v ([B,H,T,D]). MODE 1: fp32 store to C.
// ---------------------------------------------------------------------------
#define BK 32
#define LDPH 40                       // halves per row (80B, conflict-free)
#define STG_H (128 * LDPH)            // per-matrix stage, halves (5120)
#define STAGE_B (2 * STG_H * 2)       // stage bytes (20480)
#define GSMEM (2 * STAGE_B)           // 40960

template <int MODE, int Ntot, int Ktot>
__global__ void __launch_bounds__(128) mma_gemm(const __half* __restrict__ A,
                                                const __half* __restrict__ Bm,
                                                float* __restrict__ C) {
    extern __shared__ __half sm[];
    const uint32_t sb = smem_u32(sm);

    const int tid = threadIdx.x;
    const int lane = tid & 31;
    const int wid = tid >> 5;
    const int gid = lane >> 2;
    const int tig = lane & 3;
    const int wm = (wid & 1) * 64;
    const int wn = (wid >> 1) * 64;
    const int m0 = blockIdx.y * 128;
    const int n0 = blockIdx.x * 128;

    // ldmatrix fragment byte-offsets within a stage
    // A (16x16 tiles): lanes 0-15 rows, lanes>=16 k+8
    const uint32_t aoff = ((wm + (lane & 15)) * LDPH + ((lane >> 4) << 3)) * 2;
    // B (n16 x k16 tiles): lanes&16 -> n+8, lanes&8 -> k+8
    const uint32_t boff = ((wn + ((lane & 16) >> 1) + (lane & 7)) * LDPH + (lane & 8)) * 2;

    float acc[4][8][4];
#pragma unroll
    for (int i = 0; i < 4; i++)
#pragma unroll
        for (int j = 0; j < 8; j++)
#pragma unroll
            for (int v = 0; v < 4; v++) acc[i][j][v] = 0.0f;

    // 4+4 cp.async per thread per stage: 128 rows x 4 x 16B per matrix
#define ISSUE(g)                                                                        \
    do {                                                                                \
        const int _k0 = (g) * BK;                                                       \
        const uint32_t _sa = sb + ((g) & 1) * STAGE_B;                                  \
        const uint32_t _sb2 = _sa + STG_H * 2;                                          \
        _Pragma("unroll")                                                               \
        for (int _i = 0; _i < 4; _i++) {                                                \
            const int _id = tid + _i * 128;                                             \
            const int _r = _id >> 2;                                                    \
            const int _c = (_id & 3) << 3;                                              \
            cpa16(_sa + (_r * LDPH + _c) * 2, A + (size_t)(m0 + _r) * Ktot + _k0 + _c); \
            cpa16(_sb2 + (_r * LDPH + _c) * 2, Bm + (size_t)(n0 + _r) * Ktot + _k0 + _c); \
        }                                                                               \
        CP_COMMIT();                                                                    \
    } while (0)

    ISSUE(0);

    const int NITER = Ktot / BK;
#pragma unroll 1
    for (int it = 0; it < NITER; ++it) {
        CP_WAIT(0);
        __syncthreads();
        if (it + 1 < NITER) ISSUE(it + 1);

        const uint32_t stg = sb + (it & 1) * STAGE_B;
        const uint32_t ab = stg + aoff;
        const uint32_t bbv = stg + STG_H * 2 + boff;

#pragma unroll
        for (int kc = 0; kc < 2; kc++) {       // two k16 chunks per BK=32
            uint32_t af[4][4], bb[4][4];
#pragma unroll
            for (int mi = 0; mi < 4; mi++)
                ldmx4(af[mi], ab + mi * (16 * LDPH * 2) + kc * 32);
#pragma unroll
            for (int p = 0; p < 4; p++)
                ldmx4(bb[p], bbv + p * (16 * LDPH * 2) + kc * 32);
#pragma unroll
            for (int mi = 0; mi < 4; mi++)
#pragma unroll
                for (int ni = 0; ni < 8; ni++)
                    mma_f16(acc[mi][ni], af[mi], &bb[ni >> 1][(ni & 1) * 2]);
        }
    }
#undef ISSUE

    // Epilogue
#pragma unroll
    for (int mi = 0; mi < 4; mi++) {
#pragma unroll
        for (int ni = 0; ni < 8; ni++) {
            const int m = m0 + wm + mi * 16 + gid;
            const int n = n0 + wn + ni * 8 + 2 * tig;
            if (MODE == 0) {
                const int which = n >> 10;
                const int e = n & (E_ - 1);
                const int h = e >> 6;
                const int d = e & 63;
                __half* base = (which == 0) ? g_q : (which == 1) ? g_k : g_v;
#pragma unroll
                for (int rr = 0; rr < 2; rr++) {
                    const int mm = m + rr * 8;
                    const int b = mm >> 11;
                    const int t = mm & (T_ - 1);
                    const size_t idx = (((size_t)(b * H_ + h) * T_ + t) * D_ + d);
                    *((uint32_t*)base + (idx >> 1)) =
                        h2u(acc[mi][ni][2 * rr], acc[mi][ni][2 * rr + 1]);
                }
            } else {
#pragma unroll
                for (int rr = 0; rr < 2; rr++) {
                    const int mm = m + rr * 8;
                    *(float2*)(C + (size_t)mm * Ntot + n) =
                        make_float2(acc[mi][ni][2 * rr], acc[mi][ni][2 * rr + 1]);
                }
            }
        }
    }
}

// ---------------------------------------------------------------------------
// FP16 mma.sync causal flash attention.
// Block: 128 q-rows x 1 head, 256 threads (8 warps x 16 rows). K-tile 64.
// K and V both straight cp.async copies, double-buffered.
// S accum -> P via f16x2 pack (registers only); PV B-frags via ldmatrix.trans.
// smem: K[2][64][72] + V[2][64][72] halves = 36864 B.
// ---------------------------------------------------------------------------
#define ASTRH 72
#define AQB 128
#define AKB 64
#define SCL2E 0.18033688011112042f   // (1/8) * log2(e)
#define KVBUF (64 * ASTRH * 2)       // 9216 B
#define ASMEM (4 * KVBUF)

__global__ void __launch_bounds__(256) attn_mma() {
    extern __shared__ __half sm[];
    const uint32_t sb = smem_u32(sm);

    const int tid = threadIdx.x;
    const int wid = tid >> 5;
    const int lane = tid & 31;
    const int gid = lane >> 2;
    const int tig = lane & 3;

    const int bh = blockIdx.y;
    const int qb = gridDim.x - 1 - blockIdx.x;   // heavy blocks first
    const int q0 = qb * AQB;
    const int wq = wid * 16;
    const int r1 = q0 + wq + gid;
    const int r2 = r1 + 8;

    // K B-fragment byte-offset (non-trans): n=key row, k=d
    const uint32_t nkoff = ((((lane & 16) >> 1) + (lane & 7)) * ASTRH + (lane & 8)) * 2;
    // V B-fragment byte-offset (trans): rows j, cols d; lanes&8 -> j+8, lanes&16 -> d+8
    const uint32_t voff = (((lane & 8) + (lane & 7)) * ASTRH + ((lane & 16) >> 1)) * 2;

    const __half* kbase = g_k + (size_t)bh * T_ * D_;
    const __half* vbase = g_v + (size_t)bh * T_ * D_;

    // Q fragments: qf[kc] covers d = 16kc..16kc+15 for rows r1, r2
    uint32_t qf[4][4];
    {
        const uint32_t* q1 = (const uint32_t*)(g_q + ((size_t)bh * T_ + r1) * D_);
        const uint32_t* q2 = (const uint32_t*)(g_q + ((size_t)bh * T_ + r2) * D_);
#pragma unroll
        for (int kc = 0; kc < 4; kc++) {
            qf[kc][0] = q1[kc * 8 + tig];
            qf[kc][1] = q2[kc * 8 + tig];
            qf[kc][2] = q1[kc * 8 + tig + 4];
            qf[kc][3] = q2[kc * 8 + tig + 4];
        }
    }

    float o[8][4];
#pragma unroll
    for (int i = 0; i < 8; i++)
#pragma unroll
        for (int v = 0; v < 4; v++) o[i][v] = 0.0f;
    float m1 = __int_as_float(0xff800000), m2 = __int_as_float(0xff800000);
    float l1 = 0.0f, l2 = 0.0f;

    // K buf b at sb + b*KVBUF; V buf b at sb + (2+b)*KVBUF.
    // Per tile: K 64x128B + V 64x128B = 1024 x 16B; 4 cpa16/thread.
#define LOADKV(kt, buf)                                                                  \
    do {                                                                                 \
        const int _j0 = (kt) * AKB;                                                      \
        const uint32_t _kb = sb + (buf) * KVBUF;                                         \
        const uint32_t _vb = sb + (2 + (buf)) * KVBUF;                                   \
        _Pragma("unroll")                                                                \
        for (int _i = 0; _i < 2; _i++) {                                                 \
            const int _id = tid + _i * 256;                                              \
            const int _j = _id >> 3;                                                     \
            const int _c = (_id & 7) << 3;                                               \
            cpa16(_kb + (_j * ASTRH + _c) * 2, kbase + (size_t)(_j0 + _j) * D_ + _c);    \
            cpa16(_vb + (_j * ASTRH + _c) * 2, vbase + (size_t)(_j0 + _j) * D_ + _c);    \
        }                                                                                \
        CP_COMMIT();                                                                     \
    } while (0)

    LOADKV(0, 0);

    const int ntiles = (q0 + AQB) / AKB;
#pragma unroll 1
    for (int kt = 0; kt < ntiles; kt++) {
        const int j0 = kt * AKB;
        const int buf = kt & 1;

        CP_WAIT(0);          // K/V(kt) landed
        __syncthreads();     // everyone done with buffers of tile kt-1
        if (kt + 1 < ntiles) LOADKV(kt + 1, buf ^ 1);

        if (j0 <= q0 + wq + 15) {
            const uint32_t Ksb = sb + buf * KVBUF;
            const uint32_t Vsb = sb + (2 + buf) * KVBUF;

            // ---- S = Q K^T ----
            float s[8][4];
#pragma unroll
            for (int jn = 0; jn < 8; jn++)
#pragma unroll
                for (int v = 0; v < 4; v++) s[jn][v] = 0.0f;
#pragma unroll
            for (int kc = 0; kc < 4; kc++) {       // d chunks of 16
                uint32_t bb[4][4];
#pragma unroll
                for (int p = 0; p < 4; p++)        // key 16-blocks
                    ldmx4(bb[p], Ksb + nkoff + p * (16 * ASTRH * 2) + kc * 32);
#pragma unroll
                for (int jn = 0; jn < 8; jn++)
                    mma_f16(s[jn], qf[kc], &bb[jn >> 1][(jn & 1) * 2]);
            }

            // scale + causal mask
            const bool masked = (kt >= ntiles - 2);
#pragma unroll
            for (int jn = 0; jn < 8; jn++) {
                s[jn][0] *= SCL2E; s[jn][1] *= SCL2E;
                s[jn][2] *= SCL2E; s[jn][3] *= SCL2E;
                if (masked) {
                    const int c0m = j0 + jn * 8 + 2 * tig;
                    if (c0m > r1) s[jn][0] = __int_as_float(0xff800000);
                    if (c0m + 1 > r1) s[jn][1] = __int_as_float(0xff800000);
                    if (c0m > r2) s[jn][2] = __int_as_float(0xff800000);
                    if (c0m + 1 > r2) s[jn][3] = __int_as_float(0xff800000);
                }
            }

            // ---- online softmax (log2 domain) ----
            float nm1 = m1, nm2 = m2;
#pragma unroll
            for (int jn = 0; jn < 8; jn++) {
                nm1 = fmaxf(nm1, fmaxf(s[jn][0], s[jn][1]));
                nm2 = fmaxf(nm2, fmaxf(s[jn][2], s[jn][3]));
            }
            nm1 = fmaxf(nm1, __shfl_xor_sync(0xffffffffu, nm1, 1));
            nm1 = fmaxf(nm1, __shfl_xor_sync(0xffffffffu, nm1, 2));
            nm2 = fmaxf(nm2, __shfl_xor_sync(0xffffffffu, nm2, 1));
            nm2 = fmaxf(nm2, __shfl_xor_sync(0xffffffffu, nm2, 2));

            const float corr1 = ex2(m1 - nm1);
            const float corr2 = ex2(m2 - nm2);
            m1 = nm1; m2 = nm2;

            float ls1 = 0.0f, ls2 = 0.0f;
#pragma unroll
            for (int jn = 0; jn < 8; jn++) {
                s[jn][0] = ex2(s[jn][0] - nm1);
                s[jn][1] = ex2(s[jn][1] - nm1);
                s[jn][2] = ex2(s[jn][2] - nm2);
                s[jn][3] = ex2(s[jn][3] - nm2);
                ls1 += s[jn][0] + s[jn][1];
                ls2 += s[jn][2] + s[jn][3];
            }
            ls1 += __shfl_xor_sync(0xffffffffu, ls1, 1);
            ls1 += __shfl_xor_sync(0xffffffffu, ls1, 2);
            ls2 += __shfl_xor_sync(0xffffffffu, ls2, 1);
            ls2 += __shfl_xor_sync(0xffffffffu, ls2, 2);
            l1 = l1 * corr1 + ls1;
            l2 = l2 * corr2 + ls2;

#pragma unroll
            for (int dn = 0; dn < 8; dn++) {
                o[dn][0] *= corr1; o[dn][1] *= corr1;
                o[dn][2] *= corr2; o[dn][3] *= corr2;
            }

            // ---- O += P V ----
            // P A-frag for j chunk kc (16 keys) packs directly from s accums:
            // a0=(r1, j=16kc+2tig,+1)=s[2kc][0..1]; a1=(r2,..)=s[2kc][2..3];
            // a2=(r1, +8)=s[2kc+1][0..1]; a3=(r2,+8)=s[2kc+1][2..3].
#pragma unroll
            for (int kc = 0; kc < 4; kc++) {
                uint32_t pf[4];
                pf[0] = h2u(s[2 * kc][0], s[2 * kc][1]);
                pf[1] = h2u(s[2 * kc][2], s[2 * kc][3]);
                pf[2] = h2u(s[2 * kc + 1][0], s[2 * kc + 1][1]);
                pf[3] = h2u(s[2 * kc + 1][2], s[2 * kc + 1][3]);

                uint32_t vb[4][4];
#pragma unroll
                for (int p = 0; p < 4; p++)        // d 16-blocks
                    ldmx4t(vb[p], Vsb + voff + kc * (16 * ASTRH * 2) + p * 32);
#pragma unroll
                for (int dn = 0; dn < 8; dn++)
                    mma_f16(o[dn], pf, &vb[dn >> 1][(dn & 1) * 2]);
            }
        }
    }
#undef LOADKV

    // ---- write normalized fp16 output, head-reassembled [B*T, E] ----
    const float inv1 = 1.0f / l1;
    const float inv2 = 1.0f / l2;
    const int b = bh / H_;
    const int h = bh - b * H_;
    uint32_t* o1 = (uint32_t*)g_att + (((size_t)(b * T_ + r1)) * E_ + h * D_) / 2;
    uint32_t* o2 = (uint32_t*)g_att + (((size_t)(b * T_ + r2)) * E_ + h * D_) / 2;
#pragma unroll
    for (int dn = 0; dn < 8; dn++) {
        o1[dn * 4 + tig] = h2u(o[dn][0] * inv1, o[dn][1] * inv1);
        o2[dn * 4 + tig] = h2u(o[dn][2] * inv2, o[dn][3] * inv2);
    }
}

// ---------------------------------------------------------------------------
// Launch
// ---------------------------------------------------------------------------
extern "C" void kernel_launch(void* const* d_in, const int* in_sizes, int n_in,
                              void* d_out, int out_size) {
    const float* x = (const float*)d_in[0];       // [B,T,E]
    const float* w_qkv = (const float*)d_in[1];   // [3E,E]
    const float* w_proj = (const float*)d_in[2];  // [E,E]
    float* out = (float*)d_out;                   // [B,T,E]

    static bool attr_done = false;
    if (!attr_done) {
        cudaFuncSetAttribute(mma_gemm<0, 3 * E_, E_>,
                             cudaFuncAttributeMaxDynamicSharedMemorySize, GSMEM);
        cudaFuncSetAttribute(mma_gemm<1, E_, E_>,
                             cudaFuncAttributeMaxDynamicSharedMemorySize, GSMEM);
        cudaFuncSetAttribute(attn_mma, cudaFuncAttributeMaxDynamicSharedMemorySize, ASMEM);
        attr_done = true;
    }

    __half *xr, *wqkvr, *wprojr, *attp;
    cudaGetSymbolAddress((void**)&xr, g_xr);
    cudaGetSymbolAddress((void**)&wqkvr, g_wqkvr);
    cudaGetSymbolAddress((void**)&wprojr, g_wprojr);
    cudaGetSymbolAddress((void**)&attp, g_att);

    // 0) fp16 rounding prep, one launch
    round_all<<<8192, 256>>>(x, w_qkv, w_proj);

    // 1) QKV projection -> fp16 q/k/v in [B,H,T,D]   (grid 24 x 32, 128 thr)
    mma_gemm<0, 3 * E_, E_><<<dim3(3 * E_ / 128, BT_ / 128), 128, GSMEM>>>(xr, wqkvr, nullptr);

    // 2) Causal flash attention -> fp16 g_att [B*T, E]   (grid 16 x 32, 256 thr)
    attn_mma<<<dim3(T_ / AQB, B_ * H_), 256, ASMEM>>>();

    // 3) Output projection -> d_out (fp32)   (grid 8 x 32, 128 thr)
    mma_gemm<1, E_, E_><<<dim3(E_ / 128, BT_ / 128), 128, GSMEM>>>(attp, wprojr, out);
}

// round 15
// speedup vs baseline: 2.7488x; 1.0038x over previous
#include <cuda_runtime.h>
#include <cuda_fp16.h>
#include <cstdint>

// Problem constants
#define B_ 2
#define T_ 2048
#define E_ 1024
#define H_ 16
#define D_ 64
#define BT_ (B_ * T_)

// Scratch (allocation-free: __device__ globals). fp16 operand copies.
__device__ __half g_q[(size_t)B_ * H_ * T_ * D_];
__device__ __half g_k[(size_t)B_ * H_ * T_ * D_];
__device__ __half g_v[(size_t)B_ * H_ * T_ * D_];
__device__ __half g_att[(size_t)BT_ * E_];
__device__ __half g_xr[(size_t)BT_ * E_];
__device__ __half g_wqkvr[(size_t)3 * E_ * E_];
__device__ __half g_wprojr[(size_t)E_ * E_];

// ---------------------------------------------------------------------------
__device__ __forceinline__ uint32_t smem_u32(const void* p) {
    uint32_t a;
    asm("{ .reg .u64 t; cvta.to.shared.u64 t, %1; cvt.u32.u64 %0, t; }" : "=r"(a) : "l"(p));
    return a;
}
__device__ __forceinline__ float ex2(float x) {
    float r;
    asm("ex2.approx.f32 %0, %1;" : "=f"(r) : "f"(x));
    return r;
}
// pack two floats -> half2 bits (lo, hi), round-to-nearest
__device__ __forceinline__ uint32_t h2u(float lo, float hi) {
    uint32_t r;
    asm("cvt.rn.f16x2.f32 %0, %1, %2;" : "=r"(r) : "f"(hi), "f"(lo));
    return r;
}
// D(16x8,f32) += A(16x16,f16) * B(16x8,f16)   (row.col)
__device__ __forceinline__ void mma_f16(float* c, const uint32_t* a, const uint32_t* b) {
    asm volatile(
        "mma.sync.aligned.m16n8k16.row.col.f32.f16.f16.f32 "
        "{%0,%1,%2,%3}, {%4,%5,%6,%7}, {%8,%9}, {%0,%1,%2,%3};"
        : "+f"(c[0]), "+f"(c[1]), "+f"(c[2]), "+f"(c[3])
        : "r"(a[0]), "r"(a[1]), "r"(a[2]), "r"(a[3]), "r"(b[0]), "r"(b[1]));
}
__device__ __forceinline__ void ldmx4(uint32_t* r, uint32_t a) {
    asm volatile("ldmatrix.sync.aligned.m8n8.x4.shared.b16 {%0,%1,%2,%3}, [%4];"
                 : "=r"(r[0]), "=r"(r[1]), "=r"(r[2]), "=r"(r[3]) : "r"(a));
}
__device__ __forceinline__ void ldmx4t(uint32_t* r, uint32_t a) {
    asm volatile("ldmatrix.sync.aligned.m8n8.x4.trans.shared.b16 {%0,%1,%2,%3}, [%4];"
                 : "=r"(r[0]), "=r"(r[1]), "=r"(r[2]), "=r"(r[3]) : "r"(a));
}
__device__ __forceinline__ void cpa16(uint32_t s, const void* g) {
    asm volatile("cp.async.cg.shared.global [%0], [%1], 16;" :: "r"(s), "l"(g) : "memory");
}
#define CP_COMMIT() asm volatile("cp.async.commit_group;" ::: "memory")
#define CP_WAIT(n) asm volatile("cp.async.wait_group %0;" :: "n"(n) : "memory")

// ---------------------------------------------------------------------------
// Prep: round x, w_qkv, w_proj to fp16 (RN). f4 segments:
// x: [0, 1048576), wqkv: [1048576, 1835008), wproj: [1835008, 2097152)
// ---------------------------------------------------------------------------
__global__ void __launch_bounds__(256) round_all(const float* __restrict__ x,
                                                 const float* __restrict__ wq,
                                                 const float* __restrict__ wp) {
    const size_t f4 = (size_t)blockIdx.x * 256 + threadIdx.x;
    const float* src;
    __half* dst;
    size_t off;
    if (f4 < 1048576) { src = x; dst = g_xr; off = f4; }
    else if (f4 < 1835008) { src = wq; dst = g_wqkvr; off = f4 - 1048576; }
    else { src = wp; dst = g_wprojr; off = f4 - 1835008; }
    const size_t i = off * 4;
    float4 v = *(const float4*)(src + i);
    *(uint2*)(dst + i) = make_uint2(h2u(v.x, v.y), h2u(v.z, v.w));
}

// ---------------------------------------------------------------------------
// FP16 mma.sync GEMM (m16n8k16). 128 x BNt CTA tile, 128 threads
// (2x2 warps, warp tile 64 x BNt/2). BK=32, 3-stage cp.async, ldmatrix b16.
// C[m,n] = sum_k A[m,k] * Bm[n,k]; A,B fp16.
// MODE 0: store fp16 into g_q/g_k/g_v ([B,H,T,D]). MODE 1: fp32 store to C.
// ---------------------------------------------------------------------------
#define BK 32
#define LDPH 40                       // halves per row (80B, conflict-free)

template <int MODE, int Ntot, int Ktot, int BNt>
__global__ void __launch_bounds__(128) mma_gemm(const __half* __restrict__ A,
                                                const __half* __restrict__ Bm,
                                                float* __restrict__ C) {
    constexpr int WN = BNt / 2;            // warp n-span
    constexpr int NACC = WN / 8;           // 8-wide acc tiles per warp
    constexpr int NFRAG = WN / 16;         // 16-row B blocks per warp
    constexpr int STG_A_H = 128 * LDPH;    // halves
    constexpr int STG_B_H = BNt * LDPH;    // halves
    constexpr int STAGE_B = (STG_A_H + STG_B_H) * 2;  // bytes

    extern __shared__ __half sm[];
    const uint32_t sb = smem_u32(sm);

    const int tid = threadIdx.x;
    const int lane = tid & 31;
    const int wid = tid >> 5;
    const int gid = lane >> 2;
    const int tig = lane & 3;
    const int wm = (wid & 1) * 64;
    const int wn = (wid >> 1) * WN;
    const int m0 = blockIdx.y * 128;
    const int n0 = blockIdx.x * BNt;

    // ldmatrix fragment byte-offsets within a stage
    const uint32_t aoff = ((wm + (lane & 15)) * LDPH + ((lane >> 4) << 3)) * 2;
    const uint32_t boff = ((wn + ((lane & 16) >> 1) + (lane & 7)) * LDPH + (lane & 8)) * 2;

    float acc[4][NACC][4];
#pragma unroll
    for (int i = 0; i < 4; i++)
#pragma unroll
        for (int j = 0; j < NACC; j++)
#pragma unroll
            for (int v = 0; v < 4; v++) acc[i][j][v] = 0.0f;

#define ISSUE(g)                                                                        \
    do {                                                                                \
        const int _k0 = (g) * BK;                                                       \
        const uint32_t _sa = sb + ((g) % 3) * STAGE_B;                                  \
        const uint32_t _sb2 = _sa + STG_A_H * 2;                                        \
        _Pragma("unroll")                                                               \
        for (int _i = 0; _i < 4; _i++) {                                                \
            const int _id = tid + _i * 128;                                             \
            const int _r = _id >> 2;                                                    \
            const int _c = (_id & 3) << 3;                                              \
            cpa16(_sa + (_r * LDPH + _c) * 2, A + (size_t)(m0 + _r) * Ktot + _k0 + _c); \
        }                                                                               \
        _Pragma("unroll")                                                               \
        for (int _i = 0; _i < BNt / 32; _i++) {                                         \
            const int _id = tid + _i * 128;                                             \
            const int _r = _id >> 2;                                                    \
            const int _c = (_id & 3) << 3;                                              \
            cpa16(_sb2 + (_r * LDPH + _c) * 2, Bm + (size_t)(n0 + _r) * Ktot + _k0 + _c); \
        }                                                                               \
        CP_COMMIT();                                                                    \
    } while (0)

    ISSUE(0);
    ISSUE(1);

    const int NITER = Ktot / BK;
#pragma unroll 1
    for (int it = 0; it < NITER; ++it) {
        if (it + 1 < NITER) CP_WAIT(1); else CP_WAIT(0);
        __syncthreads();
        if (it + 2 < NITER) ISSUE(it + 2);

        const uint32_t stg = sb + (it % 3) * STAGE_B;
        const uint32_t ab = stg + aoff;
        const uint32_t bbv = stg + STG_A_H * 2 + boff;

#pragma unroll
        for (int kc = 0; kc < 2; kc++) {       // two k16 chunks per BK=32
            uint32_t af[4][4], bb[NFRAG][4];
#pragma unroll
            for (int mi = 0; mi < 4; mi++)
                ldmx4(af[mi], ab + mi * (16 * LDPH * 2) + kc * 32);
#pragma unroll
            for (int p = 0; p < NFRAG; p++)
                ldmx4(bb[p], bbv + p * (16 * LDPH * 2) + kc * 32);
#pragma unroll
            for (int mi = 0; mi < 4; mi++)
#pragma unroll
                for (int ni = 0; ni < NACC; ni++)
                    mma_f16(acc[mi][ni], af[mi], &bb[ni >> 1][(ni & 1) * 2]);
        }
    }
#undef ISSUE

    // Epilogue
#pragma unroll
    for (int mi = 0; mi < 4; mi++) {
#pragma unroll
        for (int ni = 0; ni < NACC; ni++) {
            const int m = m0 + wm + mi * 16 + gid;
            const int n = n0 + wn + ni * 8 + 2 * tig;
            if (MODE == 0) {
                const int which = n >> 10;
                const int e = n & (E_ - 1);
                const int h = e >> 6;
                const int d = e & 63;
                __half* base = (which == 0) ? g_q : (which == 1) ? g_k : g_v;
#pragma unroll
                for (int rr = 0; rr < 2; rr++) {
                    const int mm = m + rr * 8;
                    const int b = mm >> 11;
                    const int t = mm & (T_ - 1);
                    const size_t idx = (((size_t)(b * H_ + h) * T_ + t) * D_ + d);
                    *((uint32_t*)base + (idx >> 1)) =
                        h2u(acc[mi][ni][2 * rr], acc[mi][ni][2 * rr + 1]);
                }
            } else {
#pragma unroll
                for (int rr = 0; rr < 2; rr++) {
                    const int mm = m + rr * 8;
                    *(float2*)(C + (size_t)mm * Ntot + n) =
                        make_float2(acc[mi][ni][2 * rr], acc[mi][ni][2 * rr + 1]);
                }
            }
        }
    }
}

#define GSMEM_QKV (3 * (128 * LDPH + 128 * LDPH) * 2)   // 61440
#define GSMEM_PRJ (3 * (128 * LDPH + 64 * LDPH) * 2)    // 46080

// ---------------------------------------------------------------------------
// FP16 mma.sync causal flash attention (unchanged from R14).
// Block: 128 q-rows x 1 head, 256 threads (8 warps x 16 rows). K-tile 64.
// ---------------------------------------------------------------------------
#define ASTRH 72
#define AQB 128
#define AKB 64
#define SCL2E 0.18033688011112042f   // (1/8) * log2(e)
#define KVBUF (64 * ASTRH * 2)       // 9216 B
#define ASMEM (4 * KVBUF)

__global__ void __launch_bounds__(256) attn_mma() {
    extern __shared__ __half sm[];
    const uint32_t sb = smem_u32(sm);

    const int tid = threadIdx.x;
    const int wid = tid >> 5;
    const int lane = tid & 31;
    const int gid = lane >> 2;
    const int tig = lane & 3;

    const int bh = blockIdx.y;
    const int qb = gridDim.x - 1 - blockIdx.x;   // heavy blocks first
    const int q0 = qb * AQB;
    const int wq = wid * 16;
    const int r1 = q0 + wq + gid;
    const int r2 = r1 + 8;

    const uint32_t nkoff = ((((lane & 16) >> 1) + (lane & 7)) * ASTRH + (lane & 8)) * 2;
    const uint32_t voff = (((lane & 8) + (lane & 7)) * ASTRH + ((lane & 16) >> 1)) * 2;

    const __half* kbase = g_k + (size_t)bh * T_ * D_;
    const __half* vbase = g_v + (size_t)bh * T_ * D_;

    uint32_t qf[4][4];
    {
        const uint32_t* q1 = (const uint32_t*)(g_q + ((size_t)bh * T_ + r1) * D_);
        const uint32_t* q2 = (const uint32_t*)(g_q + ((size_t)bh * T_ + r2) * D_);
#pragma unroll
        for (int kc = 0; kc < 4; kc++) {
            qf[kc][0] = q1[kc * 8 + tig];
            qf[kc][1] = q2[kc * 8 + tig];
            qf[kc][2] = q1[kc * 8 + tig + 4];
            qf[kc][3] = q2[kc * 8 + tig + 4];
        }
    }

    float o[8][4];
#pragma unroll
    for (int i = 0; i < 8; i++)
#pragma unroll
        for (int v = 0; v < 4; v++) o[i][v] = 0.0f;
    float m1 = __int_as_float(0xff800000), m2 = __int_as_float(0xff800000);
    float l1 = 0.0f, l2 = 0.0f;

#define LOADKV(kt, buf)                                                                  \
    do {                                                                                 \
        const int _j0 = (kt) * AKB;                                                      \
        const uint32_t _kb = sb + (buf) * KVBUF;                                         \
        const uint32_t _vb = sb + (2 + (buf)) * KVBUF;                                   \
        _Pragma("unroll")                                                                \
        for (int _i = 0; _i < 2; _i++) {                                                 \
            const int _id = tid + _i * 256;                                              \
            const int _j = _id >> 3;                                                     \
            const int _c = (_id & 7) << 3;                                               \
            cpa16(_kb + (_j * ASTRH + _c) * 2, kbase + (size_t)(_j0 + _j) * D_ + _c);    \
            cpa16(_vb + (_j * ASTRH + _c) * 2, vbase + (size_t)(_j0 + _j) * D_ + _c);    \
        }                                                                                \
        CP_COMMIT();                                                                     \
    } while (0)

    LOADKV(0, 0);

    const int ntiles = (q0 + AQB) / AKB;
#pragma unroll 1
    for (int kt = 0; kt < ntiles; kt++) {
        const int j0 = kt * AKB;
        const int buf = kt & 1;

        CP_WAIT(0);
        __syncthreads();
        if (kt + 1 < ntiles) LOADKV(kt + 1, buf ^ 1);

        if (j0 <= q0 + wq + 15) {
            const uint32_t Ksb = sb + buf * KVBUF;
            const uint32_t Vsb = sb + (2 + buf) * KVBUF;

            // ---- S = Q K^T ----
            float s[8][4];
#pragma unroll
            for (int jn = 0; jn < 8; jn++)
#pragma unroll
                for (int v = 0; v < 4; v++) s[jn][v] = 0.0f;
#pragma unroll
            for (int kc = 0; kc < 4; kc++) {
                uint32_t bb[4][4];
#pragma unroll
                for (int p = 0; p < 4; p++)
                    ldmx4(bb[p], Ksb + nkoff + p * (16 * ASTRH * 2) + kc * 32);
#pragma unroll
                for (int jn = 0; jn < 8; jn++)
                    mma_f16(s[jn], qf[kc], &bb[jn >> 1][(jn & 1) * 2]);
            }

            const bool masked = (kt >= ntiles - 2);
#pragma unroll
            for (int jn = 0; jn < 8; jn++) {
                s[jn][0] *= SCL2E; s[jn][1] *= SCL2E;
                s[jn][2] *= SCL2E; s[jn][3] *= SCL2E;
                if (masked) {
                    const int c0m = j0 + jn * 8 + 2 * tig;
                    if (c0m > r1) s[jn][0] = __int_as_float(0xff800000);
                    if (c0m + 1 > r1) s[jn][1] = __int_as_float(0xff800000);
                    if (c0m > r2) s[jn][2] = __int_as_float(0xff800000);
                    if (c0m + 1 > r2) s[jn][3] = __int_as_float(0xff800000);
                }
            }

            // ---- online softmax (log2 domain) ----
            float nm1 = m1, nm2 = m2;
#pragma unroll
            for (int jn = 0; jn < 8; jn++) {
                nm1 = fmaxf(nm1, fmaxf(s[jn][0], s[jn][1]));
                nm2 = fmaxf(nm2, fmaxf(s[jn][2], s[jn][3]));
            }
            nm1 = fmaxf(nm1, __shfl_xor_sync(0xffffffffu, nm1, 1));
            nm1 = fmaxf(nm1, __shfl_xor_sync(0xffffffffu, nm1, 2));
            nm2 = fmaxf(nm2, __shfl_xor_sync(0xffffffffu, nm2, 1));
            nm2 = fmaxf(nm2, __shfl_xor_sync(0xffffffffu, nm2, 2));

            const float corr1 = ex2(m1 - nm1);
            const float corr2 = ex2(m2 - nm2);
            m1 = nm1; m2 = nm2;

            float ls1 = 0.0f, ls2 = 0.0f;
#pragma unroll
            for (int jn = 0; jn < 8; jn++) {
                s[jn][0] = ex2(s[jn][0] - nm1);
                s[jn][1] = ex2(s[jn][1] - nm1);
                s[jn][2] = ex2(s[jn][2] - nm2);
                s[jn][3] = ex2(s[jn][3] - nm2);
                ls1 += s[jn][0] + s[jn][1];
                ls2 += s[jn][2] + s[jn][3];
            }
            ls1 += __shfl_xor_sync(0xffffffffu, ls1, 1);
            ls1 += __shfl_xor_sync(0xffffffffu, ls1, 2);
            ls2 += __shfl_xor_sync(0xffffffffu, ls2, 1);
            ls2 += __shfl_xor_sync(0xffffffffu, ls2, 2);
            l1 = l1 * corr1 + ls1;
            l2 = l2 * corr2 + ls2;

#pragma unroll
            for (int dn = 0; dn < 8; dn++) {
                o[dn][0] *= corr1; o[dn][1] *= corr1;
                o[dn][2] *= corr2; o[dn][3] *= corr2;
            }

            // ---- O += P V (P packed straight from s accums) ----
#pragma unroll
            for (int kc = 0; kc < 4; kc++) {
                uint32_t pf[4];
                pf[0] = h2u(s[2 * kc][0], s[2 * kc][1]);
                pf[1] = h2u(s[2 * kc][2], s[2 * kc][3]);
                pf[2] = h2u(s[2 * kc + 1][0], s[2 * kc + 1][1]);
                pf[3] = h2u(s[2 * kc + 1][2], s[2 * kc + 1][3]);

                uint32_t vb[4][4];
#pragma unroll
                for (int p = 0; p < 4; p++)
                    ldmx4t(vb[p], Vsb + voff + kc * (16 * ASTRH * 2) + p * 32);
#pragma unroll
                for (int dn = 0; dn < 8; dn++)
                    mma_f16(o[dn], pf, &vb[dn >> 1][(dn & 1) * 2]);
            }
        }
    }
#undef LOADKV

    // ---- write normalized fp16 output, head-reassembled [B*T, E] ----
    const float inv1 = 1.0f / l1;
    const float inv2 = 1.0f / l2;
    const int b = bh / H_;
    const int h = bh - b * H_;
    uint32_t* o1 = (uint32_t*)g_att + (((size_t)(b * T_ + r1)) * E_ + h * D_) / 2;
    uint32_t* o2 = (uint32_t*)g_att + (((size_t)(b * T_ + r2)) * E_ + h * D_) / 2;
#pragma unroll
    for (int dn = 0; dn < 8; dn++) {
        o1[dn * 4 + tig] = h2u(o[dn][0] * inv1, o[dn][1] * inv1);
        o2[dn * 4 + tig] = h2u(o[dn][2] * inv2, o[dn][3] * inv2);
    }
}

// ---------------------------------------------------------------------------
// Launch
// ---------------------------------------------------------------------------
extern "C" void kernel_launch(void* const* d_in, const int* in_sizes, int n_in,
                              void* d_out, int out_size) {
    const float* x = (const float*)d_in[0];       // [B,T,E]
    const float* w_qkv = (const float*)d_in[1];   // [3E,E]
    const float* w_proj = (const float*)d_in[2];  // [E,E]
    float* out = (float*)d_out;                   // [B,T,E]

    static bool attr_done = false;
    if (!attr_done) {
        cudaFuncSetAttribute(mma_gemm<0, 3 * E_, E_, 128>,
                             cudaFuncAttributeMaxDynamicSharedMemorySize, GSMEM_QKV);
        cudaFuncSetAttribute(mma_gemm<1, E_, E_, 64>,
                             cudaFuncAttributeMaxDynamicSharedMemorySize, GSMEM_PRJ);
        cudaFuncSetAttribute(attn_mma, cudaFuncAttributeMaxDynamicSharedMemorySize, ASMEM);
        attr_done = true;
    }

    __half *xr, *wqkvr, *wprojr, *attp;
    cudaGetSymbolAddress((void**)&xr, g_xr);
    cudaGetSymbolAddress((void**)&wqkvr, g_wqkvr);
    cudaGetSymbolAddress((void**)&wprojr, g_wprojr);
    cudaGetSymbolAddress((void**)&attp, g_att);

    // 0) fp16 rounding prep, one launch
    round_all<<<8192, 256>>>(x, w_qkv, w_proj);

    // 1) QKV projection -> fp16 q/k/v in [B,H,T,D]   (grid 24 x 32, 128 thr)
    mma_gemm<0, 3 * E_, E_, 128><<<dim3(3 * E_ / 128, BT_ / 128), 128, GSMEM_QKV>>>(xr, wqkvr, nullptr);

    // 2) Causal flash attention -> fp16 g_att [B*T, E]   (grid 16 x 32, 256 thr)
    attn_mma<<<dim3(T_ / AQB, B_ * H_), 256, ASMEM>>>();

    // 3) Output projection -> d_out (fp32)   (grid 16 x 32, 128 thr)
    mma_gemm<1, E_, E_, 64><<<dim3(E_ / 64, BT_ / 128), 128, GSMEM_PRJ>>>(attp, wprojr, out);
}

// round 16
// speedup vs baseline: 3.0662x; 1.1155x over previous
#include <cuda_runtime.h>
#include <cuda_fp16.h>
#include <cstdint>

// Problem constants
#define B_ 2
#define T_ 2048
#define E_ 1024
#define H_ 16
#define D_ 64
#define BT_ (B_ * T_)

// Scratch (allocation-free: __device__ globals). fp16 operand copies.
__device__ __half g_q[(size_t)B_ * H_ * T_ * D_];
__device__ __half g_k[(size_t)B_ * H_ * T_ * D_];
__device__ __half g_v[(size_t)B_ * H_ * T_ * D_];
__device__ __half g_att[(size_t)BT_ * E_];
__device__ __half g_xr[(size_t)BT_ * E_];
__device__ __half g_wqkvr[(size_t)3 * E_ * E_];
__device__ __half g_wprojr[(size_t)E_ * E_];

// ---------------------------------------------------------------------------
__device__ __forceinline__ uint32_t smem_u32(const void* p) {
    uint32_t a;
    asm("{ .reg .u64 t; cvta.to.shared.u64 t, %1; cvt.u32.u64 %0, t; }" : "=r"(a) : "l"(p));
    return a;
}
__device__ __forceinline__ float ex2(float x) {
    float r;
    asm("ex2.approx.f32 %0, %1;" : "=f"(r) : "f"(x));
    return r;
}
// pack two floats -> half2 bits (lo, hi), round-to-nearest
__device__ __forceinline__ uint32_t h2u(float lo, float hi) {
    uint32_t r;
    asm("cvt.rn.f16x2.f32 %0, %1, %2;" : "=r"(r) : "f"(hi), "f"(lo));
    return r;
}
// D(16x8,f32) += A(16x16,f16) * B(16x8,f16)   (row.col)
__device__ __forceinline__ void mma_f16(float* c, const uint32_t* a, const uint32_t* b) {
    asm volatile(
        "mma.sync.aligned.m16n8k16.row.col.f32.f16.f16.f32 "
        "{%0,%1,%2,%3}, {%4,%5,%6,%7}, {%8,%9}, {%0,%1,%2,%3};"
        : "+f"(c[0]), "+f"(c[1]), "+f"(c[2]), "+f"(c[3])
        : "r"(a[0]), "r"(a[1]), "r"(a[2]), "r"(a[3]), "r"(b[0]), "r"(b[1]));
}
__device__ __forceinline__ void ldmx4(uint32_t* r, uint32_t a) {
    asm volatile("ldmatrix.sync.aligned.m8n8.x4.shared.b16 {%0,%1,%2,%3}, [%4];"
                 : "=r"(r[0]), "=r"(r[1]), "=r"(r[2]), "=r"(r[3]) : "r"(a));
}
__device__ __forceinline__ void ldmx4t(uint32_t* r, uint32_t a) {
    asm volatile("ldmatrix.sync.aligned.m8n8.x4.trans.shared.b16 {%0,%1,%2,%3}, [%4];"
                 : "=r"(r[0]), "=r"(r[1]), "=r"(r[2]), "=r"(r[3]) : "r"(a));
}
__device__ __forceinline__ void cpa16(uint32_t s, const void* g) {
    asm volatile("cp.async.cg.shared.global [%0], [%1], 16;" :: "r"(s), "l"(g) : "memory");
}
#define CP_COMMIT() asm volatile("cp.async.commit_group;" ::: "memory")
#define CP_WAIT(n) asm volatile("cp.async.wait_group %0;" :: "n"(n) : "memory")

// ---------------------------------------------------------------------------
// Prep: round x, w_qkv, w_proj to fp16 (RN). f4 segments:
// x: [0, 1048576), wqkv: [1048576, 1835008), wproj: [1835008, 2097152)
// ---------------------------------------------------------------------------
__global__ void __launch_bounds__(256) round_all(const float* __restrict__ x,
                                                 const float* __restrict__ wq,
                                                 const float* __restrict__ wp) {
    const size_t f4 = (size_t)blockIdx.x * 256 + threadIdx.x;
    const float* src;
    __half* dst;
    size_t off;
    if (f4 < 1048576) { src = x; dst = g_xr; off = f4; }
    else if (f4 < 1835008) { src = wq; dst = g_wqkvr; off = f4 - 1048576; }
    else { src = wp; dst = g_wprojr; off = f4 - 1835008; }
    const size_t i = off * 4;
    float4 v = *(const float4*)(src + i);
    *(uint2*)(dst + i) = make_uint2(h2u(v.x, v.y), h2u(v.z, v.w));
}

// ---------------------------------------------------------------------------
// FP16 mma.sync GEMM (m16n8k16). 128 x BNt CTA tile, 128 threads
// (2x2 warps, warp tile 64 x BNt/2). BK=64, 2-stage cp.async, ldmatrix b16.
// C[m,n] = sum_k A[m,k] * Bm[n,k]; A,B fp16.
// MODE 0: store fp16 into g_q/g_k/g_v ([B,H,T,D]). MODE 1: fp32 store to C.
// ---------------------------------------------------------------------------
#define BK 64
#define LDPH 72                       // halves per row (144B; 8-row ldmatrix conflict-free)

template <int MODE, int Ntot, int Ktot, int BNt>
__global__ void __launch_bounds__(128) mma_gemm(const __half* __restrict__ A,
                                                const __half* __restrict__ Bm,
                                                float* __restrict__ C) {
    constexpr int WN = BNt / 2;            // warp n-span
    constexpr int NACC = WN / 8;           // 8-wide acc tiles per warp
    constexpr int NFRAG = WN / 16;         // 16-row B blocks per warp
    constexpr int STG_A_H = 128 * LDPH;    // halves
    constexpr int STG_B_H = BNt * LDPH;    // halves
    constexpr int STAGE_B = (STG_A_H + STG_B_H) * 2;  // bytes

    extern __shared__ __half sm[];
    const uint32_t sb = smem_u32(sm);

    const int tid = threadIdx.x;
    const int lane = tid & 31;
    const int wid = tid >> 5;
    const int gid = lane >> 2;
    const int tig = lane & 3;
    const int wm = (wid & 1) * 64;
    const int wn = (wid >> 1) * WN;
    const int m0 = blockIdx.y * 128;
    const int n0 = blockIdx.x * BNt;

    // ldmatrix fragment byte-offsets within a stage
    const uint32_t aoff = ((wm + (lane & 15)) * LDPH + ((lane >> 4) << 3)) * 2;
    const uint32_t boff = ((wn + ((lane & 16) >> 1) + (lane & 7)) * LDPH + (lane & 8)) * 2;

    float acc[4][NACC][4];
#pragma unroll
    for (int i = 0; i < 4; i++)
#pragma unroll
        for (int j = 0; j < NACC; j++)
#pragma unroll
            for (int v = 0; v < 4; v++) acc[i][j][v] = 0.0f;

    // Per stage: A 128 rows x 8 x 16B; B BNt rows x 8 x 16B.
#define ISSUE(g)                                                                        \
    do {                                                                                \
        const int _k0 = (g) * BK;                                                       \
        const uint32_t _sa = sb + ((g) & 1) * STAGE_B;                                  \
        const uint32_t _sb2 = _sa + STG_A_H * 2;                                        \
        _Pragma("unroll")                                                               \
        for (int _i = 0; _i < 8; _i++) {                                                \
            const int _id = tid + _i * 128;                                             \
            const int _r = _id >> 3;                                                    \
            const int _c = (_id & 7) << 3;                                              \
            cpa16(_sa + (_r * LDPH + _c) * 2, A + (size_t)(m0 + _r) * Ktot + _k0 + _c); \
        }                                                                               \
        _Pragma("unroll")                                                               \
        for (int _i = 0; _i < BNt / 16; _i++) {                                         \
            const int _id = tid + _i * 128;                                             \
            const int _r = _id >> 3;                                                    \
            const int _c = (_id & 7) << 3;                                              \
            cpa16(_sb2 + (_r * LDPH + _c) * 2, Bm + (size_t)(n0 + _r) * Ktot + _k0 + _c); \
        }                                                                               \
        CP_COMMIT();                                                                    \
    } while (0)

    ISSUE(0);

    const int NITER = Ktot / BK;
#pragma unroll 1
    for (int it = 0; it < NITER; ++it) {
        CP_WAIT(0);
        __syncthreads();
        if (it + 1 < NITER) ISSUE(it + 1);

        const uint32_t stg = sb + (it & 1) * STAGE_B;
        const uint32_t ab = stg + aoff;
        const uint32_t bbv = stg + STG_A_H * 2 + boff;

#pragma unroll
        for (int kc = 0; kc < 4; kc++) {       // four k16 chunks per BK=64
            uint32_t af[4][4], bb[NFRAG][4];
#pragma unroll
            for (int mi = 0; mi < 4; mi++)
                ldmx4(af[mi], ab + mi * (16 * LDPH * 2) + kc * 32);
#pragma unroll
            for (int p = 0; p < NFRAG; p++)
                ldmx4(bb[p], bbv + p * (16 * LDPH * 2) + kc * 32);
#pragma unroll
            for (int mi = 0; mi < 4; mi++)
#pragma unroll
                for (int ni = 0; ni < NACC; ni++)
                    mma_f16(acc[mi][ni], af[mi], &bb[ni >> 1][(ni & 1) * 2]);
        }
    }
#undef ISSUE

    // Epilogue
#pragma unroll
    for (int mi = 0; mi < 4; mi++) {
#pragma unroll
        for (int ni = 0; ni < NACC; ni++) {
            const int m = m0 + wm + mi * 16 + gid;
            const int n = n0 + wn + ni * 8 + 2 * tig;
            if (MODE == 0) {
                const int which = n >> 10;
                const int e = n & (E_ - 1);
                const int h = e >> 6;
                const int d = e & 63;
                __half* base = (which == 0) ? g_q : (which == 1) ? g_k : g_v;
#pragma unroll
                for (int rr = 0; rr < 2; rr++) {
                    const int mm = m + rr * 8;
                    const int b = mm >> 11;
                    const int t = mm & (T_ - 1);
                    const size_t idx = (((size_t)(b * H_ + h) * T_ + t) * D_ + d);
                    *((uint32_t*)base + (idx >> 1)) =
                        h2u(acc[mi][ni][2 * rr], acc[mi][ni][2 * rr + 1]);
                }
            } else {
#pragma unroll
                for (int rr = 0; rr < 2; rr++) {
                    const int mm = m + rr * 8;
                    *(float2*)(C + (size_t)mm * Ntot + n) =
                        make_float2(acc[mi][ni][2 * rr], acc[mi][ni][2 * rr + 1]);
                }
            }
        }
    }
}

#define GSMEM_QKV (2 * (128 * LDPH + 128 * LDPH) * 2)   // 73728
#define GSMEM_PRJ (2 * (128 * LDPH + 64 * LDPH) * 2)    // 55296

// ---------------------------------------------------------------------------
// FP16 mma.sync causal flash attention.
// Block: 128 q-rows x 1 head, 256 threads (8 warps x 16 rows). K-tile 64.
// Deferred softmax-sum reduction: per-thread partial l, quad-reduced at end.
// ---------------------------------------------------------------------------
#define ASTRH 72
#define AQB 128
#define AKB 64
#define SCL2E 0.18033688011112042f   // (1/8) * log2(e)
#define KVBUF (64 * ASTRH * 2)       // 9216 B
#define ASMEM (4 * KVBUF)

__global__ void __launch_bounds__(256) attn_mma() {
    extern __shared__ __half sm[];
    const uint32_t sb = smem_u32(sm);

    const int tid = threadIdx.x;
    const int wid = tid >> 5;
    const int lane = tid & 31;
    const int gid = lane >> 2;
    const int tig = lane & 3;

    const int bh = blockIdx.y;
    const int qb = gridDim.x - 1 - blockIdx.x;   // heavy blocks first
    const int q0 = qb * AQB;
    const int wq = wid * 16;
    const int r1 = q0 + wq + gid;
    const int r2 = r1 + 8;

    const uint32_t nkoff = ((((lane & 16) >> 1) + (lane & 7)) * ASTRH + (lane & 8)) * 2;
    const uint32_t voff = (((lane & 8) + (lane & 7)) * ASTRH + ((lane & 16) >> 1)) * 2;

    const __half* kbase = g_k + (size_t)bh * T_ * D_;
    const __half* vbase = g_v + (size_t)bh * T_ * D_;

    uint32_t qf[4][4];
    {
        const uint32_t* q1 = (const uint32_t*)(g_q + ((size_t)bh * T_ + r1) * D_);
        const uint32_t* q2 = (const uint32_t*)(g_q + ((size_t)bh * T_ + r2) * D_);
#pragma unroll
        for (int kc = 0; kc < 4; kc++) {
            qf[kc][0] = q1[kc * 8 + tig];
            qf[kc][1] = q2[kc * 8 + tig];
            qf[kc][2] = q1[kc * 8 + tig + 4];
            qf[kc][3] = q2[kc * 8 + tig + 4];
        }
    }

    float o[8][4];
#pragma unroll
    for (int i = 0; i < 8; i++)
#pragma unroll
        for (int v = 0; v < 4; v++) o[i][v] = 0.0f;
    float m1 = __int_as_float(0xff800000), m2 = __int_as_float(0xff800000);
    float l1 = 0.0f, l2 = 0.0f;          // per-thread partial row sums

#define LOADKV(kt, buf)                                                                  \
    do {                                                                                 \
        const int _j0 = (kt) * AKB;                                                      \
        const uint32_t _kb = sb + (buf) * KVBUF;                                         \
        const uint32_t _vb = sb + (2 + (buf)) * KVBUF;                                   \
        _Pragma("unroll")                                                                \
        for (int _i = 0; _i < 2; _i++) {                                                 \
            const int _id = tid + _i * 256;                                              \
            const int _j = _id >> 3;                                                     \
            const int _c = (_id & 7) << 3;                                               \
            cpa16(_kb + (_j * ASTRH + _c) * 2, kbase + (size_t)(_j0 + _j) * D_ + _c);    \
            cpa16(_vb + (_j * ASTRH + _c) * 2, vbase + (size_t)(_j0 + _j) * D_ + _c);    \
        }                                                                                \
        CP_COMMIT();                                                                     \
    } while (0)

    LOADKV(0, 0);

    const int ntiles = (q0 + AQB) / AKB;
#pragma unroll 1
    for (int kt = 0; kt < ntiles; kt++) {
        const int j0 = kt * AKB;
        const int buf = kt & 1;

        CP_WAIT(0);
        __syncthreads();
        if (kt + 1 < ntiles) LOADKV(kt + 1, buf ^ 1);

        if (j0 <= q0 + wq + 15) {
            const uint32_t Ksb = sb + buf * KVBUF;
            const uint32_t Vsb = sb + (2 + buf) * KVBUF;

            // ---- S = Q K^T ----
            float s[8][4];
#pragma unroll
            for (int jn = 0; jn < 8; jn++)
#pragma unroll
                for (int v = 0; v < 4; v++) s[jn][v] = 0.0f;
#pragma unroll
            for (int kc = 0; kc < 4; kc++) {
                uint32_t bb[4][4];
#pragma unroll
                for (int p = 0; p < 4; p++)
                    ldmx4(bb[p], Ksb + nkoff + p * (16 * ASTRH * 2) + kc * 32);
#pragma unroll
                for (int jn = 0; jn < 8; jn++)
                    mma_f16(s[jn], qf[kc], &bb[jn >> 1][(jn & 1) * 2]);
            }

            const bool masked = (kt >= ntiles - 2);
#pragma unroll
            for (int jn = 0; jn < 8; jn++) {
                s[jn][0] *= SCL2E; s[jn][1] *= SCL2E;
                s[jn][2] *= SCL2E; s[jn][3] *= SCL2E;
                if (masked) {
                    const int c0m = j0 + jn * 8 + 2 * tig;
                    if (c0m > r1) s[jn][0] = __int_as_float(0xff800000);
                    if (c0m + 1 > r1) s[jn][1] = __int_as_float(0xff800000);
                    if (c0m > r2) s[jn][2] = __int_as_float(0xff800000);
                    if (c0m + 1 > r2) s[jn][3] = __int_as_float(0xff800000);
                }
            }

            // ---- online softmax (log2 domain), max over quad only ----
            float nm1 = m1, nm2 = m2;
#pragma unroll
            for (int jn = 0; jn < 8; jn++) {
                nm1 = fmaxf(nm1, fmaxf(s[jn][0], s[jn][1]));
                nm2 = fmaxf(nm2, fmaxf(s[jn][2], s[jn][3]));
            }
            nm1 = fmaxf(nm1, __shfl_xor_sync(0xffffffffu, nm1, 1));
            nm1 = fmaxf(nm1, __shfl_xor_sync(0xffffffffu, nm1, 2));
            nm2 = fmaxf(nm2, __shfl_xor_sync(0xffffffffu, nm2, 1));
            nm2 = fmaxf(nm2, __shfl_xor_sync(0xffffffffu, nm2, 2));

            const float corr1 = ex2(m1 - nm1);
            const float corr2 = ex2(m2 - nm2);
            m1 = nm1; m2 = nm2;

            // per-thread partial sums; quad reduction deferred to the end
            float ls1 = 0.0f, ls2 = 0.0f;
#pragma unroll
            for (int jn = 0; jn < 8; jn++) {
                s[jn][0] = ex2(s[jn][0] - nm1);
                s[jn][1] = ex2(s[jn][1] - nm1);
                s[jn][2] = ex2(s[jn][2] - nm2);
                s[jn][3] = ex2(s[jn][3] - nm2);
                ls1 += s[jn][0] + s[jn][1];
                ls2 += s[jn][2] + s[jn][3];
            }
            l1 = l1 * corr1 + ls1;
            l2 = l2 * corr2 + ls2;

#pragma unroll
            for (int dn = 0; dn < 8; dn++) {
                o[dn][0] *= corr1; o[dn][1] *= corr1;
                o[dn][2] *= corr2; o[dn][3] *= corr2;
            }

            // ---- O += P V (P packed straight from s accums) ----
#pragma unroll
            for (int kc = 0; kc < 4; kc++) {
                uint32_t pf[4];
                pf[0] = h2u(s[2 * kc][0], s[2 * kc][1]);
                pf[1] = h2u(s[2 * kc][2], s[2 * kc][3]);
                pf[2] = h2u(s[2 * kc + 1][0], s[2 * kc + 1][1]);
                pf[3] = h2u(s[2 * kc + 1][2], s[2 * kc + 1][3]);

                uint32_t vb[4][4];
#pragma unroll
                for (int p = 0; p < 4; p++)
                    ldmx4t(vb[p], Vsb + voff + kc * (16 * ASTRH * 2) + p * 32);
#pragma unroll
                for (int dn = 0; dn < 8; dn++)
                    mma_f16(o[dn], pf, &vb[dn >> 1][(dn & 1) * 2]);
            }
        }
    }
#undef LOADKV

    // ---- final l reduction across quad, then write fp16 output ----
    l1 += __shfl_xor_sync(0xffffffffu, l1, 1);
    l1 += __shfl_xor_sync(0xffffffffu, l1, 2);
    l2 += __shfl_xor_sync(0xffffffffu, l2, 1);
    l2 += __shfl_xor_sync(0xffffffffu, l2, 2);
    const float inv1 = 1.0f / l1;
    const float inv2 = 1.0f / l2;
    const int b = bh / H_;
    const int h = bh - b * H_;
    uint32_t* o1 = (uint32_t*)g_att + (((size_t)(b * T_ + r1)) * E_ + h * D_) / 2;
    uint32_t* o2 = (uint32_t*)g_att + (((size_t)(b * T_ + r2)) * E_ + h * D_) / 2;
#pragma unroll
    for (int dn = 0; dn < 8; dn++) {
        o1[dn * 4 + tig] = h2u(o[dn][0] * inv1, o[dn][1] * inv1);
        o2[dn * 4 + tig] = h2u(o[dn][2] * inv2, o[dn][3] * inv2);
    }
}

// ---------------------------------------------------------------------------
// Launch
// ---------------------------------------------------------------------------
extern "C" void kernel_launch(void* const* d_in, const int* in_sizes, int n_in,
                              void* d_out, int out_size) {
    const float* x = (const float*)d_in[0];       // [B,T,E]
    const float* w_qkv = (const float*)d_in[1];   // [3E,E]
    const float* w_proj = (const float*)d_in[2];  // [E,E]
    float* out = (float*)d_out;                   // [B,T,E]

    static bool attr_done = false;
    if (!attr_done) {
        cudaFuncSetAttribute(mma_gemm<0, 3 * E_, E_, 128>,
                             cudaFuncAttributeMaxDynamicSharedMemorySize, GSMEM_QKV);
        cudaFuncSetAttribute(mma_gemm<1, E_, E_, 64>,
                             cudaFuncAttributeMaxDynamicSharedMemorySize, GSMEM_PRJ);
        cudaFuncSetAttribute(attn_mma, cudaFuncAttributeMaxDynamicSharedMemorySize, ASMEM);
        attr_done = true;
    }

    __half *xr, *wqkvr, *wprojr, *attp;
    cudaGetSymbolAddress((void**)&xr, g_xr);
    cudaGetSymbolAddress((void**)&wqkvr, g_wqkvr);
    cudaGetSymbolAddress((void**)&wprojr, g_wprojr);
    cudaGetSymbolAddress((void**)&attp, g_att);

    // 0) fp16 rounding prep, one launch
    round_all<<<8192, 256>>>(x, w_qkv, w_proj);

    // 1) QKV projection -> fp16 q/k/v in [B,H,T,D]   (grid 24 x 32, 128 thr)
    mma_gemm<0, 3 * E_, E_, 128><<<dim3(3 * E_ / 128, BT_ / 128), 128, GSMEM_QKV>>>(xr, wqkvr, nullptr);

    // 2) Causal flash attention -> fp16 g_att [B*T, E]   (grid 16 x 32, 256 thr)
    attn_mma<<<dim3(T_ / AQB, B_ * H_), 256, ASMEM>>>();

    // 3) Output projection -> d_out (fp32)   (grid 16 x 32, 128 thr)
    mma_gemm<1, E_, E_, 64><<<dim3(E_ / 64, BT_ / 128), 128, GSMEM_PRJ>>>(attp, wprojr, out);
}

// round 17
// speedup vs baseline: 3.1263x; 1.0196x over previous
#include <cuda_runtime.h>
#include <cuda_fp16.h>
#include <cstdint>

// Problem constants
#define B_ 2
#define T_ 2048
#define E_ 1024
#define H_ 16
#define D_ 64
#define BT_ (B_ * T_)

// Scratch (allocation-free: __device__ globals). fp16 operand copies.
__device__ __half g_q[(size_t)B_ * H_ * T_ * D_];
__device__ __half g_k[(size_t)B_ * H_ * T_ * D_];
__device__ __half g_v[(size_t)B_ * H_ * T_ * D_];
__device__ __half g_att[(size_t)BT_ * E_];
__device__ __half g_xr[(size_t)BT_ * E_];
__device__ __half g_wqkvr[(size_t)3 * E_ * E_];
__device__ __half g_wprojr[(size_t)E_ * E_];

// ---------------------------------------------------------------------------
__device__ __forceinline__ uint32_t smem_u32(const void* p) {
    uint32_t a;
    asm("{ .reg .u64 t; cvta.to.shared.u64 t, %1; cvt.u32.u64 %0, t; }" : "=r"(a) : "l"(p));
    return a;
}
__device__ __forceinline__ float ex2(float x) {
    float r;
    asm("ex2.approx.f32 %0, %1;" : "=f"(r) : "f"(x));
    return r;
}
// pack two floats -> half2 bits (lo, hi), round-to-nearest
__device__ __forceinline__ uint32_t h2u(float lo, float hi) {
    uint32_t r;
    asm("cvt.rn.f16x2.f32 %0, %1, %2;" : "=r"(r) : "f"(hi), "f"(lo));
    return r;
}
// D(16x8,f32) += A(16x16,f16) * B(16x8,f16)   (row.col)
__device__ __forceinline__ void mma_f16(float* c, const uint32_t* a, const uint32_t* b) {
    asm volatile(
        "mma.sync.aligned.m16n8k16.row.col.f32.f16.f16.f32 "
        "{%0,%1,%2,%3}, {%4,%5,%6,%7}, {%8,%9}, {%0,%1,%2,%3};"
        : "+f"(c[0]), "+f"(c[1]), "+f"(c[2]), "+f"(c[3])
        : "r"(a[0]), "r"(a[1]), "r"(a[2]), "r"(a[3]), "r"(b[0]), "r"(b[1]));
}
__device__ __forceinline__ void ldmx4(uint32_t* r, uint32_t a) {
    asm volatile("ldmatrix.sync.aligned.m8n8.x4.shared.b16 {%0,%1,%2,%3}, [%4];"
                 : "=r"(r[0]), "=r"(r[1]), "=r"(r[2]), "=r"(r[3]) : "r"(a));
}
__device__ __forceinline__ void ldmx4t(uint32_t* r, uint32_t a) {
    asm volatile("ldmatrix.sync.aligned.m8n8.x4.trans.shared.b16 {%0,%1,%2,%3}, [%4];"
                 : "=r"(r[0]), "=r"(r[1]), "=r"(r[2]), "=r"(r[3]) : "r"(a));
}
__device__ __forceinline__ void cpa16(uint32_t s, const void* g) {
    asm volatile("cp.async.cg.shared.global [%0], [%1], 16;" :: "r"(s), "l"(g) : "memory");
}
#define CP_COMMIT() asm volatile("cp.async.commit_group;" ::: "memory")
#define CP_WAIT(n) asm volatile("cp.async.wait_group %0;" :: "n"(n) : "memory")

// ---------------------------------------------------------------------------
// Prep: round x, w_qkv, w_proj to fp16 (RN). f4 segments:
// x: [0, 1048576), wqkv: [1048576, 1835008), wproj: [1835008, 2097152)
// ---------------------------------------------------------------------------
__global__ void __launch_bounds__(256) round_all(const float* __restrict__ x,
                                                 const float* __restrict__ wq,
                                                 const float* __restrict__ wp) {
    const size_t f4 = (size_t)blockIdx.x * 256 + threadIdx.x;
    const float* src;
    __half* dst;
    size_t off;
    if (f4 < 1048576) { src = x; dst = g_xr; off = f4; }
    else if (f4 < 1835008) { src = wq; dst = g_wqkvr; off = f4 - 1048576; }
    else { src = wp; dst = g_wprojr; off = f4 - 1835008; }
    const size_t i = off * 4;
    float4 v = *(const float4*)(src + i);
    *(uint2*)(dst + i) = make_uint2(h2u(v.x, v.y), h2u(v.z, v.w));
}

// ---------------------------------------------------------------------------
// FP16 mma.sync GEMM (m16n8k16). 128 x BNt CTA tile, 128 threads
// (2x2 warps, warp tile 64 x BNt/2). BK=64, 2-stage cp.async, ldmatrix b16.
// C[m,n] = sum_k A[m,k] * Bm[n,k]; A,B fp16.
// MODE 0: store fp16 into g_q/g_k/g_v ([B,H,T,D]). MODE 1: fp32 store to C.
// ---------------------------------------------------------------------------
#define BK 64
#define LDPH 72                       // halves per row (144B; 8-row ldmatrix conflict-free)

template <int MODE, int Ntot, int Ktot, int BNt>
__global__ void __launch_bounds__(128) mma_gemm(const __half* __restrict__ A,
                                                const __half* __restrict__ Bm,
                                                float* __restrict__ C) {
    constexpr int WN = BNt / 2;            // warp n-span
    constexpr int NACC = WN / 8;           // 8-wide acc tiles per warp
    constexpr int NFRAG = WN / 16;         // 16-row B blocks per warp
    constexpr int STG_A_H = 128 * LDPH;    // halves
    constexpr int STG_B_H = BNt * LDPH;    // halves
    constexpr int STAGE_B = (STG_A_H + STG_B_H) * 2;  // bytes

    extern __shared__ __half sm[];
    const uint32_t sb = smem_u32(sm);

    const int tid = threadIdx.x;
    const int lane = tid & 31;
    const int wid = tid >> 5;
    const int gid = lane >> 2;
    const int tig = lane & 3;
    const int wm = (wid & 1) * 64;
    const int wn = (wid >> 1) * WN;
    const int m0 = blockIdx.y * 128;
    const int n0 = blockIdx.x * BNt;

    // ldmatrix fragment byte-offsets within a stage
    const uint32_t aoff = ((wm + (lane & 15)) * LDPH + ((lane >> 4) << 3)) * 2;
    const uint32_t boff = ((wn + ((lane & 16) >> 1) + (lane & 7)) * LDPH + (lane & 8)) * 2;

    float acc[4][NACC][4];
#pragma unroll
    for (int i = 0; i < 4; i++)
#pragma unroll
        for (int j = 0; j < NACC; j++)
#pragma unroll
            for (int v = 0; v < 4; v++) acc[i][j][v] = 0.0f;

    // Per stage: A 128 rows x 8 x 16B; B BNt rows x 8 x 16B.
#define ISSUE(g)                                                                        \
    do {                                                                                \
        const int _k0 = (g) * BK;                                                       \
        const uint32_t _sa = sb + ((g) & 1) * STAGE_B;                                  \
        const uint32_t _sb2 = _sa + STG_A_H * 2;                                        \
        _Pragma("unroll")                                                               \
        for (int _i = 0; _i < 8; _i++) {                                                \
            const int _id = tid + _i * 128;                                             \
            const int _r = _id >> 3;                                                    \
            const int _c = (_id & 7) << 3;                                              \
            cpa16(_sa + (_r * LDPH + _c) * 2, A + (size_t)(m0 + _r) * Ktot + _k0 + _c); \
        }                                                                               \
        _Pragma("unroll")                                                               \
        for (int _i = 0; _i < BNt / 16; _i++) {                                         \
            const int _id = tid + _i * 128;                                             \
            const int _r = _id >> 3;                                                    \
            const int _c = (_id & 7) << 3;                                              \
            cpa16(_sb2 + (_r * LDPH + _c) * 2, Bm + (size_t)(n0 + _r) * Ktot + _k0 + _c); \
        }                                                                               \
        CP_COMMIT();                                                                    \
    } while (0)

    ISSUE(0);

    const int NITER = Ktot / BK;
#pragma unroll 1
    for (int it = 0; it < NITER; ++it) {
        CP_WAIT(0);
        __syncthreads();
        if (it + 1 < NITER) ISSUE(it + 1);

        const uint32_t stg = sb + (it & 1) * STAGE_B;
        const uint32_t ab = stg + aoff;
        const uint32_t bbv = stg + STG_A_H * 2 + boff;

#pragma unroll
        for (int kc = 0; kc < 4; kc++) {       // four k16 chunks per BK=64
            uint32_t af[4][4], bb[NFRAG][4];
#pragma unroll
            for (int mi = 0; mi < 4; mi++)
                ldmx4(af[mi], ab + mi * (16 * LDPH * 2) + kc * 32);
#pragma unroll
            for (int p = 0; p < NFRAG; p++)
                ldmx4(bb[p], bbv + p * (16 * LDPH * 2) + kc * 32);
#pragma unroll
            for (int mi = 0; mi < 4; mi++)
#pragma unroll
                for (int ni = 0; ni < NACC; ni++)
                    mma_f16(acc[mi][ni], af[mi], &bb[ni >> 1][(ni & 1) * 2]);
        }
    }
#undef ISSUE

    // Epilogue
#pragma unroll
    for (int mi = 0; mi < 4; mi++) {
#pragma unroll
        for (int ni = 0; ni < NACC; ni++) {
            const int m = m0 + wm + mi * 16 + gid;
            const int n = n0 + wn + ni * 8 + 2 * tig;
            if (MODE == 0) {
                const int which = n >> 10;
                const int e = n & (E_ - 1);
                const int h = e >> 6;
                const int d = e & 63;
                __half* base = (which == 0) ? g_q : (which == 1) ? g_k : g_v;
#pragma unroll
                for (int rr = 0; rr < 2; rr++) {
                    const int mm = m + rr * 8;
                    const int b = mm >> 11;
                    const int t = mm & (T_ - 1);
                    const size_t idx = (((size_t)(b * H_ + h) * T_ + t) * D_ + d);
                    *((uint32_t*)base + (idx >> 1)) =
                        h2u(acc[mi][ni][2 * rr], acc[mi][ni][2 * rr + 1]);
                }
            } else {
#pragma unroll
                for (int rr = 0; rr < 2; rr++) {
                    const int mm = m + rr * 8;
                    *(float2*)(C + (size_t)mm * Ntot + n) =
                        make_float2(acc[mi][ni][2 * rr], acc[mi][ni][2 * rr + 1]);
                }
            }
        }
    }
}

#define GSMEM_G64 (2 * (128 * LDPH + 64 * LDPH) * 2)    // 55296

// ---------------------------------------------------------------------------
// FP16 mma.sync causal flash attention (unchanged from R16).
// Block: 128 q-rows x 1 head, 256 threads (8 warps x 16 rows). K-tile 64.
// Deferred softmax-sum reduction: per-thread partial l, quad-reduced at end.
// ---------------------------------------------------------------------------
#define ASTRH 72
#define AQB 128
#define AKB 64
#define SCL2E 0.18033688011112042f   // (1/8) * log2(e)
#define KVBUF (64 * ASTRH * 2)       // 9216 B
#define ASMEM (4 * KVBUF)

__global__ void __launch_bounds__(256) attn_mma() {
    extern __shared__ __half sm[];
    const uint32_t sb = smem_u32(sm);

    const int tid = threadIdx.x;
    const int wid = tid >> 5;
    const int lane = tid & 31;
    const int gid = lane >> 2;
    const int tig = lane & 3;

    const int bh = blockIdx.y;
    const int qb = gridDim.x - 1 - blockIdx.x;   // heavy blocks first
    const int q0 = qb * AQB;
    const int wq = wid * 16;
    const int r1 = q0 + wq + gid;
    const int r2 = r1 + 8;

    const uint32_t nkoff = ((((lane & 16) >> 1) + (lane & 7)) * ASTRH + (lane & 8)) * 2;
    const uint32_t voff = (((lane & 8) + (lane & 7)) * ASTRH + ((lane & 16) >> 1)) * 2;

    const __half* kbase = g_k + (size_t)bh * T_ * D_;
    const __half* vbase = g_v + (size_t)bh * T_ * D_;

    uint32_t qf[4][4];
    {
        const uint32_t* q1 = (const uint32_t*)(g_q + ((size_t)bh * T_ + r1) * D_);
        const uint32_t* q2 = (const uint32_t*)(g_q + ((size_t)bh * T_ + r2) * D_);
#pragma unroll
        for (int kc = 0; kc < 4; kc++) {
            qf[kc][0] = q1[kc * 8 + tig];
            qf[kc][1] = q2[kc * 8 + tig];
            qf[kc][2] = q1[kc * 8 + tig + 4];
            qf[kc][3] = q2[kc * 8 + tig + 4];
        }
    }

    float o[8][4];
#pragma unroll
    for (int i = 0; i < 8; i++)
#pragma unroll
        for (int v = 0; v < 4; v++) o[i][v] = 0.0f;
    float m1 = __int_as_float(0xff800000), m2 = __int_as_float(0xff800000);
    float l1 = 0.0f, l2 = 0.0f;          // per-thread partial row sums

#define LOADKV(kt, buf)                                                                  \
    do {                                                                                 \
        const int _j0 = (kt) * AKB;                                                      \
        const uint32_t _kb = sb + (buf) * KVBUF;                                         \
        const uint32_t _vb = sb + (2 + (buf)) * KVBUF;                                   \
        _Pragma("unroll")                                                                \
        for (int _i = 0; _i < 2; _i++) {                                                 \
            const int _id = tid + _i * 256;                                              \
            const int _j = _id >> 3;                                                     \
            const int _c = (_id & 7) << 3;                                               \
            cpa16(_kb + (_j * ASTRH + _c) * 2, kbase + (size_t)(_j0 + _j) * D_ + _c);    \
            cpa16(_vb + (_j * ASTRH + _c) * 2, vbase + (size_t)(_j0 + _j) * D_ + _c);    \
        }                                                                                \
        CP_COMMIT();                                                                     \
    } while (0)

    LOADKV(0, 0);

    const int ntiles = (q0 + AQB) / AKB;
#pragma unroll 1
    for (int kt = 0; kt < ntiles; kt++) {
        const int j0 = kt * AKB;
        const int buf = kt & 1;

        CP_WAIT(0);
        __syncthreads();
        if (kt + 1 < ntiles) LOADKV(kt + 1, buf ^ 1);

        if (j0 <= q0 + wq + 15) {
            const uint32_t Ksb = sb + buf * KVBUF;
            const uint32_t Vsb = sb + (2 + buf) * KVBUF;

            // ---- S = Q K^T ----
            float s[8][4];
#pragma unroll
            for (int jn = 0; jn < 8; jn++)
#pragma unroll
                for (int v = 0; v < 4; v++) s[jn][v] = 0.0f;
#pragma unroll
            for (int kc = 0; kc < 4; kc++) {
                uint32_t bb[4][4];
#pragma unroll
                for (int p = 0; p < 4; p++)
                    ldmx4(bb[p], Ksb + nkoff + p * (16 * ASTRH * 2) + kc * 32);
#pragma unroll
                for (int jn = 0; jn < 8; jn++)
                    mma_f16(s[jn], qf[kc], &bb[jn >> 1][(jn & 1) * 2]);
            }

            const bool masked = (kt >= ntiles - 2);
#pragma unroll
            for (int jn = 0; jn < 8; jn++) {
                s[jn][0] *= SCL2E; s[jn][1] *= SCL2E;
                s[jn][2] *= SCL2E; s[jn][3] *= SCL2E;
                if (masked) {
                    const int c0m = j0 + jn * 8 + 2 * tig;
                    if (c0m > r1) s[jn][0] = __int_as_float(0xff800000);
                    if (c0m + 1 > r1) s[jn][1] = __int_as_float(0xff800000);
                    if (c0m > r2) s[jn][2] = __int_as_float(0xff800000);
                    if (c0m + 1 > r2) s[jn][3] = __int_as_float(0xff800000);
                }
            }

            // ---- online softmax (log2 domain), max over quad only ----
            float nm1 = m1, nm2 = m2;
#pragma unroll
            for (int jn = 0; jn < 8; jn++) {
                nm1 = fmaxf(nm1, fmaxf(s[jn][0], s[jn][1]));
                nm2 = fmaxf(nm2, fmaxf(s[jn][2], s[jn][3]));
            }
            nm1 = fmaxf(nm1, __shfl_xor_sync(0xffffffffu, nm1, 1));
            nm1 = fmaxf(nm1, __shfl_xor_sync(0xffffffffu, nm1, 2));
            nm2 = fmaxf(nm2, __shfl_xor_sync(0xffffffffu, nm2, 1));
            nm2 = fmaxf(nm2, __shfl_xor_sync(0xffffffffu, nm2, 2));

            const float corr1 = ex2(m1 - nm1);
            const float corr2 = ex2(m2 - nm2);
            m1 = nm1; m2 = nm2;

            // per-thread partial sums; quad reduction deferred to the end
            float ls1 = 0.0f, ls2 = 0.0f;
#pragma unroll
            for (int jn = 0; jn < 8; jn++) {
                s[jn][0] = ex2(s[jn][0] - nm1);
                s[jn][1] = ex2(s[jn][1] - nm1);
                s[jn][2] = ex2(s[jn][2] - nm2);
                s[jn][3] = ex2(s[jn][3] - nm2);
                ls1 += s[jn][0] + s[jn][1];
                ls2 += s[jn][2] + s[jn][3];
            }
            l1 = l1 * corr1 + ls1;
            l2 = l2 * corr2 + ls2;

#pragma unroll
            for (int dn = 0; dn < 8; dn++) {
                o[dn][0] *= corr1; o[dn][1] *= corr1;
                o[dn][2] *= corr2; o[dn][3] *= corr2;
            }

            // ---- O += P V (P packed straight from s accums) ----
#pragma unroll
            for (int kc = 0; kc < 4; kc++) {
                uint32_t pf[4];
                pf[0] = h2u(s[2 * kc][0], s[2 * kc][1]);
                pf[1] = h2u(s[2 * kc][2], s[2 * kc][3]);
                pf[2] = h2u(s[2 * kc + 1][0], s[2 * kc + 1][1]);
                pf[3] = h2u(s[2 * kc + 1][2], s[2 * kc + 1][3]);

                uint32_t vb[4][4];
#pragma unroll
                for (int p = 0; p < 4; p++)
                    ldmx4t(vb[p], Vsb + voff + kc * (16 * ASTRH * 2) + p * 32);
#pragma unroll
                for (int dn = 0; dn < 8; dn++)
                    mma_f16(o[dn], pf, &vb[dn >> 1][(dn & 1) * 2]);
            }
        }
    }
#undef LOADKV

    // ---- final l reduction across quad, then write fp16 output ----
    l1 += __shfl_xor_sync(0xffffffffu, l1, 1);
    l1 += __shfl_xor_sync(0xffffffffu, l1, 2);
    l2 += __shfl_xor_sync(0xffffffffu, l2, 1);
    l2 += __shfl_xor_sync(0xffffffffu, l2, 2);
    const float inv1 = 1.0f / l1;
    const float inv2 = 1.0f / l2;
    const int b = bh / H_;
    const int h = bh - b * H_;
    uint32_t* o1 = (uint32_t*)g_att + (((size_t)(b * T_ + r1)) * E_ + h * D_) / 2;
    uint32_t* o2 = (uint32_t*)g_att + (((size_t)(b * T_ + r2)) * E_ + h * D_) / 2;
#pragma unroll
    for (int dn = 0; dn < 8; dn++) {
        o1[dn * 4 + tig] = h2u(o[dn][0] * inv1, o[dn][1] * inv1);
        o2[dn * 4 + tig] = h2u(o[dn][2] * inv2, o[dn][3] * inv2);
    }
}

// ---------------------------------------------------------------------------
// Launch
// ---------------------------------------------------------------------------
extern "C" void kernel_launch(void* const* d_in, const int* in_sizes, int n_in,
                              void* d_out, int out_size) {
    const float* x = (const float*)d_in[0];       // [B,T,E]
    const float* w_qkv = (const float*)d_in[1];   // [3E,E]
    const float* w_proj = (const float*)d_in[2];  // [E,E]
    float* out = (float*)d_out;                   // [B,T,E]

    static bool attr_done = false;
    if (!attr_done) {
        cudaFuncSetAttribute(mma_gemm<0, 3 * E_, E_, 64>,
                             cudaFuncAttributeMaxDynamicSharedMemorySize, GSMEM_G64);
        cudaFuncSetAttribute(mma_gemm<1, E_, E_, 64>,
                             cudaFuncAttributeMaxDynamicSharedMemorySize, GSMEM_G64);
        cudaFuncSetAttribute(attn_mma, cudaFuncAttributeMaxDynamicSharedMemorySize, ASMEM);
        attr_done = true;
    }

    __half *xr, *wqkvr, *wprojr, *attp;
    cudaGetSymbolAddress((void**)&xr, g_xr);
    cudaGetSymbolAddress((void**)&wqkvr, g_wqkvr);
    cudaGetSymbolAddress((void**)&wprojr, g_wprojr);
    cudaGetSymbolAddress((void**)&attp, g_att);

    // 0) fp16 rounding prep, one launch
    round_all<<<8192, 256>>>(x, w_qkv, w_proj);

    // 1) QKV projection -> fp16 q/k/v in [B,H,T,D]   (grid 48 x 32, 128 thr)
    mma_gemm<0, 3 * E_, E_, 64><<<dim3(3 * E_ / 64, BT_ / 128), 128, GSMEM_G64>>>(xr, wqkvr, nullptr);

    // 2) Causal flash attention -> fp16 g_att [B*T, E]   (grid 16 x 32, 256 thr)
    attn_mma<<<dim3(T_ / AQB, B_ * H_), 256, ASMEM>>>();

    // 3) Output projection -> d_out (fp32)   (grid 16 x 32, 128 thr)
    mma_gemm<1, E_, E_, 64><<<dim3(E_ / 64, BT_ / 128), 128, GSMEM_G64>>>(attp, wprojr, out);
}